// round 1
// baseline (speedup 1.0000x reference)
#include <cuda_runtime.h>

#define NMAX 50000

// ---------------- scratch (static device arrays: allocation-free) ----------
__device__ float g_agg[NMAX * 128];
__device__ float g_delta[NMAX * 3];
__device__ float g_deg[NMAX];
__device__ int   g_is64;

__device__ __forceinline__ float silu_f(float v) {
    return v / (1.f + __expf(-v));
}

// ---------------- dtype probe for edge_index (int32 vs int64) --------------
// If int64 (values in [0, 50000) >= 0), every odd 32-bit word of the first 64
// words is the zero high-half. For int32 random indices P(all zero) ~ 0.
__global__ void detect_kernel(const unsigned int* __restrict__ w) {
    if (threadIdx.x == 0) {
        int all0 = 1;
#pragma unroll
        for (int i = 1; i < 64; i += 2) all0 &= (w[i] == 0u);
        g_is64 = all0;
    }
}

__global__ void zero_kernel(int n) {
    int i = blockIdx.x * blockDim.x + threadIdx.x;
    if (i < n * 128) g_agg[i] = 0.f;
    if (i < n * 3)   g_delta[i] = 0.f;
    if (i < n)       g_deg[i] = 0.f;
}

// ---------------- fused edge kernel ----------------------------------------
// 64 edges/block, 256 threads. Per-thread microkernel: 4 channels x 8 edges.
// smem: s_in[64][264] (edge_in, later reused as msg[64][132]),
//       s_t1[64][132], rel/dist/dst/src side arrays.
#define EDGE_SMEM_FLOATS (64*264 + 64*132 + 192 + 64 + 64 + 64)
#define EDGE_SMEM_BYTES  (EDGE_SMEM_FLOATS * 4)

__global__ __launch_bounds__(256, 2) void edge_kernel(
    const float* __restrict__ h, const float* __restrict__ x,
    const void*  __restrict__ eidx, const float* __restrict__ eattr,
    const float* __restrict__ ew1, const float* __restrict__ eb1,
    const float* __restrict__ ew2, const float* __restrict__ eb2,
    const float* __restrict__ cw1, const float* __restrict__ cb1,
    const float* __restrict__ cw2, const float* __restrict__ cb2,
    int E)
{
    extern __shared__ float smem[];
    float* s_in   = smem;                    // [64][264]
    float* s_t1   = smem + 64 * 264;         // [64][132]
    float* s_rel  = s_t1 + 64 * 132;         // [64][3]
    float* s_dist = s_rel + 192;             // [64]
    int*   s_dst  = (int*)(s_dist + 64);     // [64]
    int*   s_src  = s_dst + 64;              // [64]

    const int tid = threadIdx.x;
    const int e0  = blockIdx.x * 64;

    // ---- stage 1: indices, x-derived features, edge_attr ----
    if (tid < 64) {
        int ge = e0 + tid;
        int dI = -1, sI = 0;
        float rx = 0.f, ry = 0.f, rz = 0.f, dsq = 1e-8f;
        float4 ea = make_float4(0.f, 0.f, 0.f, 0.f);
        if (ge < E) {
            if (g_is64) {
                const long long* p = (const long long*)eidx;
                sI = (int)p[ge]; dI = (int)p[E + ge];
            } else {
                const int* p = (const int*)eidx;
                sI = p[ge]; dI = p[E + ge];
            }
            const float* xd = x + (size_t)dI * 3;
            const float* xs = x + (size_t)sI * 3;
            rx = xd[0] - xs[0]; ry = xd[1] - xs[1]; rz = xd[2] - xs[2];
            dsq = fmaxf(rx * rx + ry * ry + rz * rz, 1e-8f);
            ea = ((const float4*)eattr)[ge];
        }
        s_dst[tid] = dI; s_src[tid] = sI;
        s_rel[tid * 3 + 0] = rx; s_rel[tid * 3 + 1] = ry; s_rel[tid * 3 + 2] = rz;
        s_dist[tid] = sqrtf(dsq);
        float* row = s_in + tid * 264;
        row[256] = dsq;
        row[257] = ea.x; row[258] = ea.y; row[259] = ea.z; row[260] = ea.w;
        row[261] = 0.f; row[262] = 0.f; row[263] = 0.f;
    }
    __syncthreads();

    // ---- stage 2: gather h[dst], h[src] rows into shared ----
    for (int i = tid; i < 64 * 32; i += 256) {
        int e = i >> 5, c = i & 31;
        int dI = s_dst[e], sI = s_src[e];
        float4 vd = make_float4(0.f, 0.f, 0.f, 0.f), vs = vd;
        if (dI >= 0) {
            vd = ((const float4*)h)[(size_t)dI * 32 + c];
            vs = ((const float4*)h)[(size_t)sI * 32 + c];
        }
        *(float4*)(s_in + e * 264 + c * 4) = vd;
        *(float4*)(s_in + e * 264 + 128 + c * 4) = vs;
    }
    __syncthreads();

    const int jg = tid & 31;    // channel group: channels 4*jg .. 4*jg+3
    const int eg = tid >> 5;    // edge group:    edges   8*eg .. 8*eg+7
    const float* sA = s_in + eg * 8 * 264;

    // ---- layer 1: [64,261] @ ew1[261,128] ----
    float4 acc[8];
#pragma unroll
    for (int e = 0; e < 8; e++) acc[e] = make_float4(0.f, 0.f, 0.f, 0.f);

    const float4* W1 = (const float4*)ew1;
#pragma unroll 2
    for (int k4 = 0; k4 < 65; k4++) {
        const int kb = k4 * 4;
        float4 w0 = __ldg(W1 + (kb + 0) * 32 + jg);
        float4 w1 = __ldg(W1 + (kb + 1) * 32 + jg);
        float4 w2 = __ldg(W1 + (kb + 2) * 32 + jg);
        float4 w3 = __ldg(W1 + (kb + 3) * 32 + jg);
#pragma unroll
        for (int e = 0; e < 8; e++) {
            float4 a = *(const float4*)(sA + e * 264 + kb);
            acc[e].x = fmaf(a.x,w0.x,fmaf(a.y,w1.x,fmaf(a.z,w2.x,fmaf(a.w,w3.x,acc[e].x))));
            acc[e].y = fmaf(a.x,w0.y,fmaf(a.y,w1.y,fmaf(a.z,w2.y,fmaf(a.w,w3.y,acc[e].y))));
            acc[e].z = fmaf(a.x,w0.z,fmaf(a.y,w1.z,fmaf(a.z,w2.z,fmaf(a.w,w3.z,acc[e].z))));
            acc[e].w = fmaf(a.x,w0.w,fmaf(a.y,w1.w,fmaf(a.z,w2.w,fmaf(a.w,w3.w,acc[e].w))));
        }
    }
    {   // tail k = 260
        float4 wt = __ldg(W1 + 260 * 32 + jg);
#pragma unroll
        for (int e = 0; e < 8; e++) {
            float a = sA[e * 264 + 260];
            acc[e].x = fmaf(a, wt.x, acc[e].x);
            acc[e].y = fmaf(a, wt.y, acc[e].y);
            acc[e].z = fmaf(a, wt.z, acc[e].z);
            acc[e].w = fmaf(a, wt.w, acc[e].w);
        }
    }
    {
        float4 b1 = __ldg((const float4*)eb1 + jg);
#pragma unroll
        for (int e = 0; e < 8; e++) {
            float4 v;
            v.x = silu_f(acc[e].x + b1.x);
            v.y = silu_f(acc[e].y + b1.y);
            v.z = silu_f(acc[e].z + b1.z);
            v.w = silu_f(acc[e].w + b1.w);
            *(float4*)(s_t1 + (eg * 8 + e) * 132 + jg * 4) = v;
        }
    }
    __syncthreads();

    // ---- layer 2: t1[64,128] @ ew2[128,128] -> msg, + atomic agg ----
#pragma unroll
    for (int e = 0; e < 8; e++) acc[e] = make_float4(0.f, 0.f, 0.f, 0.f);
    const float4* W2 = (const float4*)ew2;
    const float* sB = s_t1 + eg * 8 * 132;
#pragma unroll 2
    for (int k4 = 0; k4 < 32; k4++) {
        const int kb = k4 * 4;
        float4 w0 = __ldg(W2 + (kb + 0) * 32 + jg);
        float4 w1 = __ldg(W2 + (kb + 1) * 32 + jg);
        float4 w2 = __ldg(W2 + (kb + 2) * 32 + jg);
        float4 w3 = __ldg(W2 + (kb + 3) * 32 + jg);
#pragma unroll
        for (int e = 0; e < 8; e++) {
            float4 a = *(const float4*)(sB + e * 132 + kb);
            acc[e].x = fmaf(a.x,w0.x,fmaf(a.y,w1.x,fmaf(a.z,w2.x,fmaf(a.w,w3.x,acc[e].x))));
            acc[e].y = fmaf(a.x,w0.y,fmaf(a.y,w1.y,fmaf(a.z,w2.y,fmaf(a.w,w3.y,acc[e].y))));
            acc[e].z = fmaf(a.x,w0.z,fmaf(a.y,w1.z,fmaf(a.z,w2.z,fmaf(a.w,w3.z,acc[e].z))));
            acc[e].w = fmaf(a.x,w0.w,fmaf(a.y,w1.w,fmaf(a.z,w2.w,fmaf(a.w,w3.w,acc[e].w))));
        }
    }
    float* s_msg = s_in;  // reuse (layer-1 reads done), pitch 132
    {
        float4 b2 = __ldg((const float4*)eb2 + jg);
#pragma unroll
        for (int e = 0; e < 8; e++) {
            int ee = eg * 8 + e;
            float4 m;
            m.x = silu_f(acc[e].x + b2.x);
            m.y = silu_f(acc[e].y + b2.y);
            m.z = silu_f(acc[e].z + b2.z);
            m.w = silu_f(acc[e].w + b2.w);
            *(float4*)(s_msg + ee * 132 + jg * 4) = m;
            int dI = s_dst[ee];
            if (dI >= 0) {
                float* ap = g_agg + (size_t)dI * 128 + jg * 4;
                atomicAdd(ap + 0, m.x);
                atomicAdd(ap + 1, m.y);
                atomicAdd(ap + 2, m.z);
                atomicAdd(ap + 3, m.w);
            }
        }
    }
    __syncthreads();

    // ---- coord MLP: c = silu(msg @ cw1[128,64] + cb1); w = c @ cw2 + cb2 ----
    const int jc = tid & 15;   // channels 4*jc .. 4*jc+3 (of 64)
    const int ec = tid >> 4;   // edges 4*ec .. 4*ec+3
    float4 acc3[4];
#pragma unroll
    for (int e = 0; e < 4; e++) acc3[e] = make_float4(0.f, 0.f, 0.f, 0.f);
    const float4* C1 = (const float4*)cw1;   // row k: C1[k*16 + jc]
    const float* sM = s_msg + ec * 4 * 132;
#pragma unroll 2
    for (int k4 = 0; k4 < 32; k4++) {
        const int kb = k4 * 4;
        float4 w0 = __ldg(C1 + (kb + 0) * 16 + jc);
        float4 w1 = __ldg(C1 + (kb + 1) * 16 + jc);
        float4 w2 = __ldg(C1 + (kb + 2) * 16 + jc);
        float4 w3 = __ldg(C1 + (kb + 3) * 16 + jc);
#pragma unroll
        for (int e = 0; e < 4; e++) {
            float4 a = *(const float4*)(sM + e * 132 + kb);
            acc3[e].x = fmaf(a.x,w0.x,fmaf(a.y,w1.x,fmaf(a.z,w2.x,fmaf(a.w,w3.x,acc3[e].x))));
            acc3[e].y = fmaf(a.x,w0.y,fmaf(a.y,w1.y,fmaf(a.z,w2.y,fmaf(a.w,w3.y,acc3[e].y))));
            acc3[e].z = fmaf(a.x,w0.z,fmaf(a.y,w1.z,fmaf(a.z,w2.z,fmaf(a.w,w3.z,acc3[e].z))));
            acc3[e].w = fmaf(a.x,w0.w,fmaf(a.y,w1.w,fmaf(a.z,w2.w,fmaf(a.w,w3.w,acc3[e].w))));
        }
    }
    float4 bc = __ldg((const float4*)cb1 + jc);
    float4 c2 = __ldg((const float4*)cw2 + jc);
    float part[4];
#pragma unroll
    for (int e = 0; e < 4; e++) {
        float cx = silu_f(acc3[e].x + bc.x);
        float cy = silu_f(acc3[e].y + bc.y);
        float cz = silu_f(acc3[e].z + bc.z);
        float cw_ = silu_f(acc3[e].w + bc.w);
        part[e] = cx * c2.x + cy * c2.y + cz * c2.z + cw_ * c2.w;
    }
#pragma unroll
    for (int off = 8; off > 0; off >>= 1) {
#pragma unroll
        for (int e = 0; e < 4; e++)
            part[e] += __shfl_xor_sync(0xffffffffu, part[e], off, 16);
    }
    if (jc == 0) {
        float cb2v = __ldg(cb2);
#pragma unroll
        for (int e = 0; e < 4; e++) {
            int ee = ec * 4 + e;
            int dI = s_dst[ee];
            if (dI >= 0) {
                float wv = part[e] + cb2v;
                float f = wv / (s_dist[ee] + 1.f);
                atomicAdd(&g_delta[dI * 3 + 0], s_rel[ee * 3 + 0] * f);
                atomicAdd(&g_delta[dI * 3 + 1], s_rel[ee * 3 + 1] * f);
                atomicAdd(&g_delta[dI * 3 + 2], s_rel[ee * 3 + 2] * f);
                atomicAdd(&g_deg[dI], 1.f);
            }
        }
    }
}

// ---------------- node kernel: node MLP + residual + LayerNorm -------------
#define NODE_SMEM_FLOATS (64*256 + 64*132)
#define NODE_SMEM_BYTES  (NODE_SMEM_FLOATS * 4)

__global__ __launch_bounds__(256, 2) void node_kernel(
    const float* __restrict__ h,
    const float* __restrict__ nw1, const float* __restrict__ nb1,
    const float* __restrict__ nw2, const float* __restrict__ nb2,
    const float* __restrict__ ln_g, const float* __restrict__ ln_b,
    float* __restrict__ out, int N)
{
    extern __shared__ float smem[];
    float* s_in = smem;             // [64][256] = [h | agg]
    float* s_t1 = smem + 64 * 256;  // [64][132]
    const int tid = threadIdx.x;
    const int n0  = blockIdx.x * 64;

    for (int i = tid; i < 64 * 32; i += 256) {
        int e = i >> 5, c = i & 31;
        int n = n0 + e;
        float4 hv = make_float4(0.f, 0.f, 0.f, 0.f), av = hv;
        if (n < N) {
            hv = ((const float4*)h)[(size_t)n * 32 + c];
            av = ((const float4*)g_agg)[(size_t)n * 32 + c];
        }
        *(float4*)(s_in + e * 256 + c * 4) = hv;
        *(float4*)(s_in + e * 256 + 128 + c * 4) = av;
    }
    __syncthreads();

    const int jg = tid & 31;
    const int eg = tid >> 5;
    const float* sA = s_in + eg * 8 * 256;

    float4 acc[8];
#pragma unroll
    for (int e = 0; e < 8; e++) acc[e] = make_float4(0.f, 0.f, 0.f, 0.f);
    const float4* W1 = (const float4*)nw1;
#pragma unroll 2
    for (int k4 = 0; k4 < 64; k4++) {
        const int kb = k4 * 4;
        float4 w0 = __ldg(W1 + (kb + 0) * 32 + jg);
        float4 w1 = __ldg(W1 + (kb + 1) * 32 + jg);
        float4 w2 = __ldg(W1 + (kb + 2) * 32 + jg);
        float4 w3 = __ldg(W1 + (kb + 3) * 32 + jg);
#pragma unroll
        for (int e = 0; e < 8; e++) {
            float4 a = *(const float4*)(sA + e * 256 + kb);
            acc[e].x = fmaf(a.x,w0.x,fmaf(a.y,w1.x,fmaf(a.z,w2.x,fmaf(a.w,w3.x,acc[e].x))));
            acc[e].y = fmaf(a.x,w0.y,fmaf(a.y,w1.y,fmaf(a.z,w2.y,fmaf(a.w,w3.y,acc[e].y))));
            acc[e].z = fmaf(a.x,w0.z,fmaf(a.y,w1.z,fmaf(a.z,w2.z,fmaf(a.w,w3.z,acc[e].z))));
            acc[e].w = fmaf(a.x,w0.w,fmaf(a.y,w1.w,fmaf(a.z,w2.w,fmaf(a.w,w3.w,acc[e].w))));
        }
    }
    {
        float4 b1 = __ldg((const float4*)nb1 + jg);
#pragma unroll
        for (int e = 0; e < 8; e++) {
            float4 v;
            v.x = silu_f(acc[e].x + b1.x);
            v.y = silu_f(acc[e].y + b1.y);
            v.z = silu_f(acc[e].z + b1.z);
            v.w = silu_f(acc[e].w + b1.w);
            *(float4*)(s_t1 + (eg * 8 + e) * 132 + jg * 4) = v;
        }
    }
    __syncthreads();

#pragma unroll
    for (int e = 0; e < 8; e++) acc[e] = make_float4(0.f, 0.f, 0.f, 0.f);
    const float4* W2 = (const float4*)nw2;
    const float* sB = s_t1 + eg * 8 * 132;
#pragma unroll 2
    for (int k4 = 0; k4 < 32; k4++) {
        const int kb = k4 * 4;
        float4 w0 = __ldg(W2 + (kb + 0) * 32 + jg);
        float4 w1 = __ldg(W2 + (kb + 1) * 32 + jg);
        float4 w2 = __ldg(W2 + (kb + 2) * 32 + jg);
        float4 w3 = __ldg(W2 + (kb + 3) * 32 + jg);
#pragma unroll
        for (int e = 0; e < 8; e++) {
            float4 a = *(const float4*)(sB + e * 132 + kb);
            acc[e].x = fmaf(a.x,w0.x,fmaf(a.y,w1.x,fmaf(a.z,w2.x,fmaf(a.w,w3.x,acc[e].x))));
            acc[e].y = fmaf(a.x,w0.y,fmaf(a.y,w1.y,fmaf(a.z,w2.y,fmaf(a.w,w3.y,acc[e].y))));
            acc[e].z = fmaf(a.x,w0.z,fmaf(a.y,w1.z,fmaf(a.z,w2.z,fmaf(a.w,w3.z,acc[e].z))));
            acc[e].w = fmaf(a.x,w0.w,fmaf(a.y,w1.w,fmaf(a.z,w2.w,fmaf(a.w,w3.w,acc[e].w))));
        }
    }
    {
        float4 b2 = __ldg((const float4*)nb2 + jg);
        float4 g4 = __ldg((const float4*)ln_g + jg);
        float4 bb = __ldg((const float4*)ln_b + jg);
#pragma unroll
        for (int e = 0; e < 8; e++) {
            float4 r = *(const float4*)(sA + e * 256 + jg * 4);   // residual h
            float4 o;
            o.x = acc[e].x + b2.x + r.x;
            o.y = acc[e].y + b2.y + r.y;
            o.z = acc[e].z + b2.z + r.z;
            o.w = acc[e].w + b2.w + r.w;
            float s = o.x + o.y + o.z + o.w;
#pragma unroll
            for (int off = 16; off > 0; off >>= 1)
                s += __shfl_xor_sync(0xffffffffu, s, off);
            float mean = s * (1.f / 128.f);
            float dx = o.x - mean, dy = o.y - mean, dz = o.z - mean, dw = o.w - mean;
            float q = dx * dx + dy * dy + dz * dz + dw * dw;
#pragma unroll
            for (int off = 16; off > 0; off >>= 1)
                q += __shfl_xor_sync(0xffffffffu, q, off);
            float inv = rsqrtf(q * (1.f / 128.f) + 1e-5f);
            float4 y;
            y.x = dx * inv * g4.x + bb.x;
            y.y = dy * inv * g4.y + bb.y;
            y.z = dz * inv * g4.z + bb.z;
            y.w = dw * inv * g4.w + bb.w;
            int n = n0 + eg * 8 + e;
            if (n < N) ((float4*)out)[(size_t)n * 32 + jg] = y;
        }
    }
}

// ---------------- x output -------------------------------------------------
__global__ void coord_out_kernel(const float* __restrict__ x,
                                 const float* __restrict__ logit,
                                 float* __restrict__ out_x, int N)
{
    int n = blockIdx.x * blockDim.x + threadIdx.x;
    if (n < N) {
        float scale = 1.f / (1.f + expf(-logit[0]));
        float dg = fmaxf(g_deg[n], 1.f);
        float inv = scale / dg;
        out_x[n * 3 + 0] = x[n * 3 + 0] + g_delta[n * 3 + 0] * inv;
        out_x[n * 3 + 1] = x[n * 3 + 1] + g_delta[n * 3 + 1] * inv;
        out_x[n * 3 + 2] = x[n * 3 + 2] + g_delta[n * 3 + 2] * inv;
    }
}

// ---------------- launcher --------------------------------------------------
extern "C" void kernel_launch(void* const* d_in, const int* in_sizes, int n_in,
                              void* d_out, int out_size)
{
    const float* h   = (const float*)d_in[0];
    const float* x   = (const float*)d_in[1];
    const void*  ei  = d_in[2];
    const float* ea  = (const float*)d_in[3];
    const float* ew1 = (const float*)d_in[4];
    const float* eb1 = (const float*)d_in[5];
    const float* ew2 = (const float*)d_in[6];
    const float* eb2 = (const float*)d_in[7];
    const float* nw1 = (const float*)d_in[8];
    const float* nb1 = (const float*)d_in[9];
    const float* nw2 = (const float*)d_in[10];
    const float* nb2 = (const float*)d_in[11];
    const float* cw1 = (const float*)d_in[12];
    const float* cb1 = (const float*)d_in[13];
    const float* cw2 = (const float*)d_in[14];
    const float* cb2 = (const float*)d_in[15];
    const float* lgt = (const float*)d_in[16];
    const float* lng = (const float*)d_in[17];
    const float* lnb = (const float*)d_in[18];

    const int N = in_sizes[0] / 128;  // h is [N,128]
    const int E = in_sizes[3] / 4;    // edge_attr is [E,4]

    float* out_h = (float*)d_out;
    float* out_x = out_h + (size_t)N * 128;

    cudaFuncSetAttribute(edge_kernel, cudaFuncAttributeMaxDynamicSharedMemorySize,
                         EDGE_SMEM_BYTES);
    cudaFuncSetAttribute(node_kernel, cudaFuncAttributeMaxDynamicSharedMemorySize,
                         NODE_SMEM_BYTES);

    detect_kernel<<<1, 32>>>((const unsigned int*)ei);
    zero_kernel<<<(N * 128 + 255) / 256, 256>>>(N);
    edge_kernel<<<(E + 63) / 64, 256, EDGE_SMEM_BYTES>>>(
        h, x, ei, ea, ew1, eb1, ew2, eb2, cw1, cb1, cw2, cb2, E);
    node_kernel<<<(N + 63) / 64, 256, NODE_SMEM_BYTES>>>(
        h, nw1, nb1, nw2, nb2, lng, lnb, out_h, N);
    coord_out_kernel<<<(N + 255) / 256, 256>>>(x, lgt, out_x, N);
}

// round 2
// speedup vs baseline: 2.0601x; 2.0601x over previous
#include <cuda_runtime.h>

#define NMAX 50000

// ---------------- scratch (static device arrays: allocation-free) ----------
__device__ float g_agg[NMAX * 128];
__device__ float g_P1[NMAX * 128];     // h @ ew1[0:128]   + eb1
__device__ float g_P2[NMAX * 128];     // h @ ew1[128:256]
__device__ float g_delta[NMAX * 3];
__device__ float g_deg[NMAX];
__device__ int   g_is64;
__device__ int   g_skip_coord;

__device__ __forceinline__ float silu_f(float v) {
    return v / (1.f + __expf(-v));
}

// ---------------- probes: edge_index dtype, coord-MLP zero shortcut --------
__global__ void detect_kernel(const unsigned int* __restrict__ w,
                              const float* __restrict__ cw2,
                              const float* __restrict__ cb2) {
    if (threadIdx.x == 0) {
        int all0 = 1;
#pragma unroll
        for (int i = 1; i < 64; i += 2) all0 &= (w[i] == 0u);
        g_is64 = all0;
        int z = (cb2[0] == 0.f);
        for (int i = 0; i < 64; i++) z &= (cw2[i] == 0.f);
        g_skip_coord = z;
    }
}

__global__ void zero_kernel(int n) {
    int i = blockIdx.x * blockDim.x + threadIdx.x;
    if (i < n * 128) g_agg[i] = 0.f;
    if (i < n * 3)   g_delta[i] = 0.f;
    if (i < n)       g_deg[i] = 0.f;
}

// ---------------- projection kernel: P1 = h@W_d + b1, P2 = h@W_s ------------
// 64 nodes/block, 256 threads; per thread 8 nodes x 4 channels x 2 outputs.
#define PROJ_SMEM_FLOATS (64*132)
#define PROJ_SMEM_BYTES  (PROJ_SMEM_FLOATS * 4)

__global__ __launch_bounds__(256, 2) void proj_kernel(
    const float* __restrict__ h,
    const float* __restrict__ ew1, const float* __restrict__ eb1, int N)
{
    extern __shared__ float smem[];
    float* s_h = smem;  // [64][132]
    const int tid = threadIdx.x;
    const int n0  = blockIdx.x * 64;

    for (int i = tid; i < 64 * 32; i += 256) {
        int e = i >> 5, c = i & 31;
        int n = n0 + e;
        float4 v = make_float4(0.f, 0.f, 0.f, 0.f);
        if (n < N) v = ((const float4*)h)[(size_t)n * 32 + c];
        *(float4*)(s_h + e * 132 + c * 4) = v;
    }
    __syncthreads();

    const int jg = tid & 31;
    const int eg = tid >> 5;
    const float* sA = s_h + eg * 8 * 132;

    float4 accP[8], accQ[8];
#pragma unroll
    for (int e = 0; e < 8; e++) {
        accP[e] = make_float4(0.f, 0.f, 0.f, 0.f);
        accQ[e] = make_float4(0.f, 0.f, 0.f, 0.f);
    }
    const float4* Wd = (const float4*)ew1;                    // rows 0..127
    const float4* Ws = (const float4*)(ew1 + 128 * 128);      // rows 128..255
#pragma unroll 2
    for (int k4 = 0; k4 < 32; k4++) {
        const int kb = k4 * 4;
        float4 d0 = __ldg(Wd + (kb + 0) * 32 + jg);
        float4 d1 = __ldg(Wd + (kb + 1) * 32 + jg);
        float4 d2 = __ldg(Wd + (kb + 2) * 32 + jg);
        float4 d3 = __ldg(Wd + (kb + 3) * 32 + jg);
        float4 s0 = __ldg(Ws + (kb + 0) * 32 + jg);
        float4 s1 = __ldg(Ws + (kb + 1) * 32 + jg);
        float4 s2 = __ldg(Ws + (kb + 2) * 32 + jg);
        float4 s3 = __ldg(Ws + (kb + 3) * 32 + jg);
#pragma unroll
        for (int e = 0; e < 8; e++) {
            float4 a = *(const float4*)(sA + e * 132 + kb);
            accP[e].x = fmaf(a.x,d0.x,fmaf(a.y,d1.x,fmaf(a.z,d2.x,fmaf(a.w,d3.x,accP[e].x))));
            accP[e].y = fmaf(a.x,d0.y,fmaf(a.y,d1.y,fmaf(a.z,d2.y,fmaf(a.w,d3.y,accP[e].y))));
            accP[e].z = fmaf(a.x,d0.z,fmaf(a.y,d1.z,fmaf(a.z,d2.z,fmaf(a.w,d3.z,accP[e].z))));
            accP[e].w = fmaf(a.x,d0.w,fmaf(a.y,d1.w,fmaf(a.z,d2.w,fmaf(a.w,d3.w,accP[e].w))));
            accQ[e].x = fmaf(a.x,s0.x,fmaf(a.y,s1.x,fmaf(a.z,s2.x,fmaf(a.w,s3.x,accQ[e].x))));
            accQ[e].y = fmaf(a.x,s0.y,fmaf(a.y,s1.y,fmaf(a.z,s2.y,fmaf(a.w,s3.y,accQ[e].y))));
            accQ[e].z = fmaf(a.x,s0.z,fmaf(a.y,s1.z,fmaf(a.z,s2.z,fmaf(a.w,s3.z,accQ[e].z))));
            accQ[e].w = fmaf(a.x,s0.w,fmaf(a.y,s1.w,fmaf(a.z,s2.w,fmaf(a.w,s3.w,accQ[e].w))));
        }
    }
    float4 b1 = __ldg((const float4*)eb1 + jg);
#pragma unroll
    for (int e = 0; e < 8; e++) {
        int n = n0 + eg * 8 + e;
        if (n < N) {
            float4 p = accP[e];
            p.x += b1.x; p.y += b1.y; p.z += b1.z; p.w += b1.w;
            ((float4*)g_P1)[(size_t)n * 32 + jg] = p;
            ((float4*)g_P2)[(size_t)n * 32 + jg] = accQ[e];
        }
    }
}

// ---------------- fused edge kernel ----------------------------------------
// 64 edges/block, 256 threads. Layer-1 replaced by gathered projections.
#define EDGE_SMEM_FLOATS (64*132 + 64*132 + 192 + 64 + 64 + 256 + 64 + 64)
#define EDGE_SMEM_BYTES  (EDGE_SMEM_FLOATS * 4)

__global__ __launch_bounds__(256, 2) void edge_kernel(
    const float* __restrict__ x,
    const void*  __restrict__ eidx, const float* __restrict__ eattr,
    const float* __restrict__ ew1,
    const float* __restrict__ ew2, const float* __restrict__ eb2,
    const float* __restrict__ cw1, const float* __restrict__ cb1,
    const float* __restrict__ cw2, const float* __restrict__ cb2,
    int E)
{
    extern __shared__ float smem[];
    float* s_pre  = smem;                    // [64][132]; later reused as msg
    float* s_t1   = smem + 64 * 132;         // [64][132]
    float* s_rel  = s_t1 + 64 * 132;         // [64][3]
    float* s_dist = s_rel + 192;             // [64]
    float* s_dsq  = s_dist + 64;             // [64]
    float* s_ea   = s_dsq + 64;              // [64][4]
    int*   s_dst  = (int*)(s_ea + 256);      // [64]
    int*   s_src  = s_dst + 64;              // [64]

    const int tid = threadIdx.x;
    const int e0  = blockIdx.x * 64;

    // ---- stage 1: indices, x-derived features, edge_attr ----
    if (tid < 64) {
        int ge = e0 + tid;
        int dI = -1, sI = 0;
        float rx = 0.f, ry = 0.f, rz = 0.f, dsq = 1e-8f;
        float4 ea = make_float4(0.f, 0.f, 0.f, 0.f);
        if (ge < E) {
            if (g_is64) {
                const long long* p = (const long long*)eidx;
                sI = (int)p[ge]; dI = (int)p[E + ge];
            } else {
                const int* p = (const int*)eidx;
                sI = p[ge]; dI = p[E + ge];
            }
            const float* xd = x + (size_t)dI * 3;
            const float* xs = x + (size_t)sI * 3;
            rx = xd[0] - xs[0]; ry = xd[1] - xs[1]; rz = xd[2] - xs[2];
            dsq = fmaxf(rx * rx + ry * ry + rz * rz, 1e-8f);
            ea = ((const float4*)eattr)[ge];
        }
        s_dst[tid] = dI; s_src[tid] = sI;
        s_rel[tid * 3 + 0] = rx; s_rel[tid * 3 + 1] = ry; s_rel[tid * 3 + 2] = rz;
        s_dist[tid] = sqrtf(dsq);
        s_dsq[tid] = dsq;
        *(float4*)(s_ea + tid * 4) = ea;
    }
    __syncthreads();

    // ---- stage 2: gather P1[dst] + P2[src] (layer-1 linear part) ----
    for (int i = tid; i < 64 * 32; i += 256) {
        int e = i >> 5, c = i & 31;
        int dI = s_dst[e];
        float4 v = make_float4(0.f, 0.f, 0.f, 0.f);
        if (dI >= 0) {
            float4 a = ((const float4*)g_P1)[(size_t)dI * 32 + c];
            float4 b = ((const float4*)g_P2)[(size_t)s_src[e] * 32 + c];
            v.x = a.x + b.x; v.y = a.y + b.y; v.z = a.z + b.z; v.w = a.w + b.w;
        }
        *(float4*)(s_pre + e * 132 + c * 4) = v;
    }
    __syncthreads();

    const int jg = tid & 31;    // channel group: channels 4*jg .. 4*jg+3
    const int eg = tid >> 5;    // edge group:    edges   8*eg .. 8*eg+7

    // ---- stage 3: finish layer-1 (dsq / edge_attr rows) + SiLU -> t1 ----
    {
        const float4* W1 = (const float4*)ew1;
        float4 wd = __ldg(W1 + 256 * 32 + jg);   // dist_sq row
        float4 a0 = __ldg(W1 + 257 * 32 + jg);   // edge_attr rows
        float4 a1 = __ldg(W1 + 258 * 32 + jg);
        float4 a2 = __ldg(W1 + 259 * 32 + jg);
        float4 a3 = __ldg(W1 + 260 * 32 + jg);
#pragma unroll
        for (int e = 0; e < 8; e++) {
            int ee = eg * 8 + e;
            float4 p = *(const float4*)(s_pre + ee * 132 + jg * 4);
            float ds = s_dsq[ee];
            float4 ea = *(const float4*)(s_ea + ee * 4);
            float4 v;
            v.x = fmaf(ds,wd.x,fmaf(ea.x,a0.x,fmaf(ea.y,a1.x,fmaf(ea.z,a2.x,fmaf(ea.w,a3.x,p.x)))));
            v.y = fmaf(ds,wd.y,fmaf(ea.x,a0.y,fmaf(ea.y,a1.y,fmaf(ea.z,a2.y,fmaf(ea.w,a3.y,p.y)))));
            v.z = fmaf(ds,wd.z,fmaf(ea.x,a0.z,fmaf(ea.y,a1.z,fmaf(ea.z,a2.z,fmaf(ea.w,a3.z,p.z)))));
            v.w = fmaf(ds,wd.w,fmaf(ea.x,a0.w,fmaf(ea.y,a1.w,fmaf(ea.z,a2.w,fmaf(ea.w,a3.w,p.w)))));
            v.x = silu_f(v.x); v.y = silu_f(v.y); v.z = silu_f(v.z); v.w = silu_f(v.w);
            *(float4*)(s_t1 + ee * 132 + jg * 4) = v;
        }
    }
    __syncthreads();

    // ---- stage 4: layer 2: t1[64,128] @ ew2[128,128] -> msg, + atomic agg --
    float4 acc[8];
#pragma unroll
    for (int e = 0; e < 8; e++) acc[e] = make_float4(0.f, 0.f, 0.f, 0.f);
    const float4* W2 = (const float4*)ew2;
    const float* sB = s_t1 + eg * 8 * 132;
#pragma unroll 2
    for (int k4 = 0; k4 < 32; k4++) {
        const int kb = k4 * 4;
        float4 w0 = __ldg(W2 + (kb + 0) * 32 + jg);
        float4 w1 = __ldg(W2 + (kb + 1) * 32 + jg);
        float4 w2 = __ldg(W2 + (kb + 2) * 32 + jg);
        float4 w3 = __ldg(W2 + (kb + 3) * 32 + jg);
#pragma unroll
        for (int e = 0; e < 8; e++) {
            float4 a = *(const float4*)(sB + e * 132 + kb);
            acc[e].x = fmaf(a.x,w0.x,fmaf(a.y,w1.x,fmaf(a.z,w2.x,fmaf(a.w,w3.x,acc[e].x))));
            acc[e].y = fmaf(a.x,w0.y,fmaf(a.y,w1.y,fmaf(a.z,w2.y,fmaf(a.w,w3.y,acc[e].y))));
            acc[e].z = fmaf(a.x,w0.z,fmaf(a.y,w1.z,fmaf(a.z,w2.z,fmaf(a.w,w3.z,acc[e].z))));
            acc[e].w = fmaf(a.x,w0.w,fmaf(a.y,w1.w,fmaf(a.z,w2.w,fmaf(a.w,w3.w,acc[e].w))));
        }
    }
    float* s_msg = s_pre;  // reuse (gather reads done), pitch 132
    {
        float4 b2 = __ldg((const float4*)eb2 + jg);
#pragma unroll
        for (int e = 0; e < 8; e++) {
            int ee = eg * 8 + e;
            float4 m;
            m.x = silu_f(acc[e].x + b2.x);
            m.y = silu_f(acc[e].y + b2.y);
            m.z = silu_f(acc[e].z + b2.z);
            m.w = silu_f(acc[e].w + b2.w);
            *(float4*)(s_msg + ee * 132 + jg * 4) = m;
            int dI = s_dst[ee];
            if (dI >= 0) {
                float* ap = g_agg + (size_t)dI * 128 + jg * 4;
                atomicAdd(ap + 0, m.x);
                atomicAdd(ap + 1, m.y);
                atomicAdd(ap + 2, m.z);
                atomicAdd(ap + 3, m.w);
            }
        }
    }
    __syncthreads();

    if (g_skip_coord) return;   // uniform branch; cw2==0 && cb2==0 => w==0

    // ---- stage 5: coord MLP: c = silu(msg @ cw1 + cb1); w = c @ cw2 + cb2 --
    const int jc = tid & 15;   // channels 4*jc .. 4*jc+3 (of 64)
    const int ec = tid >> 4;   // edges 4*ec .. 4*ec+3
    float4 acc3[4];
#pragma unroll
    for (int e = 0; e < 4; e++) acc3[e] = make_float4(0.f, 0.f, 0.f, 0.f);
    const float4* C1 = (const float4*)cw1;
    const float* sM = s_msg + ec * 4 * 132;
#pragma unroll 2
    for (int k4 = 0; k4 < 32; k4++) {
        const int kb = k4 * 4;
        float4 w0 = __ldg(C1 + (kb + 0) * 16 + jc);
        float4 w1 = __ldg(C1 + (kb + 1) * 16 + jc);
        float4 w2 = __ldg(C1 + (kb + 2) * 16 + jc);
        float4 w3 = __ldg(C1 + (kb + 3) * 16 + jc);
#pragma unroll
        for (int e = 0; e < 4; e++) {
            float4 a = *(const float4*)(sM + e * 132 + kb);
            acc3[e].x = fmaf(a.x,w0.x,fmaf(a.y,w1.x,fmaf(a.z,w2.x,fmaf(a.w,w3.x,acc3[e].x))));
            acc3[e].y = fmaf(a.x,w0.y,fmaf(a.y,w1.y,fmaf(a.z,w2.y,fmaf(a.w,w3.y,acc3[e].y))));
            acc3[e].z = fmaf(a.x,w0.z,fmaf(a.y,w1.z,fmaf(a.z,w2.z,fmaf(a.w,w3.z,acc3[e].z))));
            acc3[e].w = fmaf(a.x,w0.w,fmaf(a.y,w1.w,fmaf(a.z,w2.w,fmaf(a.w,w3.w,acc3[e].w))));
        }
    }
    float4 bc = __ldg((const float4*)cb1 + jc);
    float4 c2 = __ldg((const float4*)cw2 + jc);
    float part[4];
#pragma unroll
    for (int e = 0; e < 4; e++) {
        float cx = silu_f(acc3[e].x + bc.x);
        float cy = silu_f(acc3[e].y + bc.y);
        float cz = silu_f(acc3[e].z + bc.z);
        float cw_ = silu_f(acc3[e].w + bc.w);
        part[e] = cx * c2.x + cy * c2.y + cz * c2.z + cw_ * c2.w;
    }
#pragma unroll
    for (int off = 8; off > 0; off >>= 1) {
#pragma unroll
        for (int e = 0; e < 4; e++)
            part[e] += __shfl_xor_sync(0xffffffffu, part[e], off, 16);
    }
    if (jc == 0) {
        float cb2v = __ldg(cb2);
#pragma unroll
        for (int e = 0; e < 4; e++) {
            int ee = ec * 4 + e;
            int dI = s_dst[ee];
            if (dI >= 0) {
                float wv = part[e] + cb2v;
                float f = wv / (s_dist[ee] + 1.f);
                atomicAdd(&g_delta[dI * 3 + 0], s_rel[ee * 3 + 0] * f);
                atomicAdd(&g_delta[dI * 3 + 1], s_rel[ee * 3 + 1] * f);
                atomicAdd(&g_delta[dI * 3 + 2], s_rel[ee * 3 + 2] * f);
                atomicAdd(&g_deg[dI], 1.f);
            }
        }
    }
}

// ---------------- node kernel: node MLP + residual + LayerNorm -------------
#define NODE_SMEM_FLOATS (64*256 + 64*132)
#define NODE_SMEM_BYTES  (NODE_SMEM_FLOATS * 4)

__global__ __launch_bounds__(256, 2) void node_kernel(
    const float* __restrict__ h,
    const float* __restrict__ nw1, const float* __restrict__ nb1,
    const float* __restrict__ nw2, const float* __restrict__ nb2,
    const float* __restrict__ ln_g, const float* __restrict__ ln_b,
    float* __restrict__ out, int N)
{
    extern __shared__ float smem[];
    float* s_in = smem;             // [64][256] = [h | agg]
    float* s_t1 = smem + 64 * 256;  // [64][132]
    const int tid = threadIdx.x;
    const int n0  = blockIdx.x * 64;

    for (int i = tid; i < 64 * 32; i += 256) {
        int e = i >> 5, c = i & 31;
        int n = n0 + e;
        float4 hv = make_float4(0.f, 0.f, 0.f, 0.f), av = hv;
        if (n < N) {
            hv = ((const float4*)h)[(size_t)n * 32 + c];
            av = ((const float4*)g_agg)[(size_t)n * 32 + c];
        }
        *(float4*)(s_in + e * 256 + c * 4) = hv;
        *(float4*)(s_in + e * 256 + 128 + c * 4) = av;
    }
    __syncthreads();

    const int jg = tid & 31;
    const int eg = tid >> 5;
    const float* sA = s_in + eg * 8 * 256;

    float4 acc[8];
#pragma unroll
    for (int e = 0; e < 8; e++) acc[e] = make_float4(0.f, 0.f, 0.f, 0.f);
    const float4* W1 = (const float4*)nw1;
#pragma unroll 2
    for (int k4 = 0; k4 < 64; k4++) {
        const int kb = k4 * 4;
        float4 w0 = __ldg(W1 + (kb + 0) * 32 + jg);
        float4 w1 = __ldg(W1 + (kb + 1) * 32 + jg);
        float4 w2 = __ldg(W1 + (kb + 2) * 32 + jg);
        float4 w3 = __ldg(W1 + (kb + 3) * 32 + jg);
#pragma unroll
        for (int e = 0; e < 8; e++) {
            float4 a = *(const float4*)(sA + e * 256 + kb);
            acc[e].x = fmaf(a.x,w0.x,fmaf(a.y,w1.x,fmaf(a.z,w2.x,fmaf(a.w,w3.x,acc[e].x))));
            acc[e].y = fmaf(a.x,w0.y,fmaf(a.y,w1.y,fmaf(a.z,w2.y,fmaf(a.w,w3.y,acc[e].y))));
            acc[e].z = fmaf(a.x,w0.z,fmaf(a.y,w1.z,fmaf(a.z,w2.z,fmaf(a.w,w3.z,acc[e].z))));
            acc[e].w = fmaf(a.x,w0.w,fmaf(a.y,w1.w,fmaf(a.z,w2.w,fmaf(a.w,w3.w,acc[e].w))));
        }
    }
    {
        float4 b1 = __ldg((const float4*)nb1 + jg);
#pragma unroll
        for (int e = 0; e < 8; e++) {
            float4 v;
            v.x = silu_f(acc[e].x + b1.x);
            v.y = silu_f(acc[e].y + b1.y);
            v.z = silu_f(acc[e].z + b1.z);
            v.w = silu_f(acc[e].w + b1.w);
            *(float4*)(s_t1 + (eg * 8 + e) * 132 + jg * 4) = v;
        }
    }
    __syncthreads();

#pragma unroll
    for (int e = 0; e < 8; e++) acc[e] = make_float4(0.f, 0.f, 0.f, 0.f);
    const float4* W2 = (const float4*)nw2;
    const float* sB = s_t1 + eg * 8 * 132;
#pragma unroll 2
    for (int k4 = 0; k4 < 32; k4++) {
        const int kb = k4 * 4;
        float4 w0 = __ldg(W2 + (kb + 0) * 32 + jg);
        float4 w1 = __ldg(W2 + (kb + 1) * 32 + jg);
        float4 w2 = __ldg(W2 + (kb + 2) * 32 + jg);
        float4 w3 = __ldg(W2 + (kb + 3) * 32 + jg);
#pragma unroll
        for (int e = 0; e < 8; e++) {
            float4 a = *(const float4*)(sB + e * 132 + kb);
            acc[e].x = fmaf(a.x,w0.x,fmaf(a.y,w1.x,fmaf(a.z,w2.x,fmaf(a.w,w3.x,acc[e].x))));
            acc[e].y = fmaf(a.x,w0.y,fmaf(a.y,w1.y,fmaf(a.z,w2.y,fmaf(a.w,w3.y,acc[e].y))));
            acc[e].z = fmaf(a.x,w0.z,fmaf(a.y,w1.z,fmaf(a.z,w2.z,fmaf(a.w,w3.z,acc[e].z))));
            acc[e].w = fmaf(a.x,w0.w,fmaf(a.y,w1.w,fmaf(a.z,w2.w,fmaf(a.w,w3.w,acc[e].w))));
        }
    }
    {
        float4 b2 = __ldg((const float4*)nb2 + jg);
        float4 g4 = __ldg((const float4*)ln_g + jg);
        float4 bb = __ldg((const float4*)ln_b + jg);
#pragma unroll
        for (int e = 0; e < 8; e++) {
            float4 r = *(const float4*)(sA + e * 256 + jg * 4);   // residual h
            float4 o;
            o.x = acc[e].x + b2.x + r.x;
            o.y = acc[e].y + b2.y + r.y;
            o.z = acc[e].z + b2.z + r.z;
            o.w = acc[e].w + b2.w + r.w;
            float s = o.x + o.y + o.z + o.w;
#pragma unroll
            for (int off = 16; off > 0; off >>= 1)
                s += __shfl_xor_sync(0xffffffffu, s, off);
            float mean = s * (1.f / 128.f);
            float dx = o.x - mean, dy = o.y - mean, dz = o.z - mean, dw = o.w - mean;
            float q = dx * dx + dy * dy + dz * dz + dw * dw;
#pragma unroll
            for (int off = 16; off > 0; off >>= 1)
                q += __shfl_xor_sync(0xffffffffu, q, off);
            float inv = rsqrtf(q * (1.f / 128.f) + 1e-5f);
            float4 y;
            y.x = dx * inv * g4.x + bb.x;
            y.y = dy * inv * g4.y + bb.y;
            y.z = dz * inv * g4.z + bb.z;
            y.w = dw * inv * g4.w + bb.w;
            int n = n0 + eg * 8 + e;
            if (n < N) ((float4*)out)[(size_t)n * 32 + jg] = y;
        }
    }
}

// ---------------- x output -------------------------------------------------
__global__ void coord_out_kernel(const float* __restrict__ x,
                                 const float* __restrict__ logit,
                                 float* __restrict__ out_x, int N)
{
    int n = blockIdx.x * blockDim.x + threadIdx.x;
    if (n < N) {
        if (g_skip_coord) {
            out_x[n * 3 + 0] = x[n * 3 + 0];
            out_x[n * 3 + 1] = x[n * 3 + 1];
            out_x[n * 3 + 2] = x[n * 3 + 2];
        } else {
            float scale = 1.f / (1.f + expf(-logit[0]));
            float dg = fmaxf(g_deg[n], 1.f);
            float inv = scale / dg;
            out_x[n * 3 + 0] = x[n * 3 + 0] + g_delta[n * 3 + 0] * inv;
            out_x[n * 3 + 1] = x[n * 3 + 1] + g_delta[n * 3 + 1] * inv;
            out_x[n * 3 + 2] = x[n * 3 + 2] + g_delta[n * 3 + 2] * inv;
        }
    }
}

// ---------------- launcher --------------------------------------------------
extern "C" void kernel_launch(void* const* d_in, const int* in_sizes, int n_in,
                              void* d_out, int out_size)
{
    const float* h   = (const float*)d_in[0];
    const float* x   = (const float*)d_in[1];
    const void*  ei  = d_in[2];
    const float* ea  = (const float*)d_in[3];
    const float* ew1 = (const float*)d_in[4];
    const float* eb1 = (const float*)d_in[5];
    const float* ew2 = (const float*)d_in[6];
    const float* eb2 = (const float*)d_in[7];
    const float* nw1 = (const float*)d_in[8];
    const float* nb1 = (const float*)d_in[9];
    const float* nw2 = (const float*)d_in[10];
    const float* nb2 = (const float*)d_in[11];
    const float* cw1 = (const float*)d_in[12];
    const float* cb1 = (const float*)d_in[13];
    const float* cw2 = (const float*)d_in[14];
    const float* cb2 = (const float*)d_in[15];
    const float* lgt = (const float*)d_in[16];
    const float* lng = (const float*)d_in[17];
    const float* lnb = (const float*)d_in[18];

    const int N = in_sizes[0] / 128;  // h is [N,128]
    const int E = in_sizes[3] / 4;    // edge_attr is [E,4]

    float* out_h = (float*)d_out;
    float* out_x = out_h + (size_t)N * 128;

    cudaFuncSetAttribute(proj_kernel, cudaFuncAttributeMaxDynamicSharedMemorySize,
                         PROJ_SMEM_BYTES);
    cudaFuncSetAttribute(edge_kernel, cudaFuncAttributeMaxDynamicSharedMemorySize,
                         EDGE_SMEM_BYTES);
    cudaFuncSetAttribute(node_kernel, cudaFuncAttributeMaxDynamicSharedMemorySize,
                         NODE_SMEM_BYTES);

    detect_kernel<<<1, 32>>>((const unsigned int*)ei, cw2, cb2);
    zero_kernel<<<(N * 128 + 255) / 256, 256>>>(N);
    proj_kernel<<<(N + 63) / 64, 256, PROJ_SMEM_BYTES>>>(h, ew1, eb1, N);
    edge_kernel<<<(E + 63) / 64, 256, EDGE_SMEM_BYTES>>>(
        x, ei, ea, ew1, ew2, eb2, cw1, cb1, cw2, cb2, E);
    node_kernel<<<(N + 63) / 64, 256, NODE_SMEM_BYTES>>>(
        h, nw1, nb1, nw2, nb2, lng, lnb, out_h, N);
    coord_out_kernel<<<(N + 255) / 256, 256>>>(x, lgt, out_x, N);
}

// round 5
// speedup vs baseline: 2.1839x; 1.0601x over previous
#include <cuda_runtime.h>
#include <cuda_bf16.h>
#include <cstdint>

#define NMAX 50000

// single shared-memory symbol for all kernels (nvcc merges extern __shared__)
extern __shared__ __align__(1024) char smem_raw[];

// ---------------- scratch (static device arrays: allocation-free) ----------
__device__ float g_agg[NMAX * 128];
__device__ float g_P1[NMAX * 128];     // h @ ew1[0:128]   + eb1
__device__ float g_P2[NMAX * 128];     // h @ ew1[128:256]
__device__ float g_delta[NMAX * 3];
__device__ float g_deg[NMAX];
__device__ int   g_is64;
__device__ int   g_skip_coord;
// ew2^T in bf16 hi/lo, plain row-major [n][k] (n=out channel, k=in channel)
__device__ __align__(16) unsigned short g_Bhi[16384];
__device__ __align__(16) unsigned short g_Blo[16384];

__device__ __forceinline__ float silu_f(float v) {
    return v / (1.f + __expf(-v));
}

// ---------------- ptx helpers ----------------------------------------------
#define LDSM_X4(r, addr) \
    asm volatile("ldmatrix.sync.aligned.m8n8.x4.shared.b16 {%0,%1,%2,%3}, [%4];" \
        : "=r"((r)[0]), "=r"((r)[1]), "=r"((r)[2]), "=r"((r)[3]) : "r"(addr))

__device__ __forceinline__ void mma16816(float* c, const uint32_t* a, const uint32_t* b) {
    asm volatile("mma.sync.aligned.m16n8k16.row.col.f32.bf16.bf16.f32 "
        "{%0,%1,%2,%3}, {%4,%5,%6,%7}, {%8,%9}, {%0,%1,%2,%3};"
        : "+f"(c[0]), "+f"(c[1]), "+f"(c[2]), "+f"(c[3])
        : "r"(a[0]), "r"(a[1]), "r"(a[2]), "r"(a[3]), "r"(b[0]), "r"(b[1]));
}

__device__ __forceinline__ void red_add_v2(float* p, float a, float b) {
    asm volatile("red.global.add.v2.f32 [%0], {%1, %2};"
        :: "l"(p), "f"(a), "f"(b) : "memory");
}

// ---------------- probes ----------------------------------------------------
__global__ void detect_kernel(const unsigned int* __restrict__ w,
                              const float* __restrict__ cw2,
                              const float* __restrict__ cb2) {
    if (threadIdx.x == 0) {
        int all0 = 1;
#pragma unroll
        for (int i = 1; i < 64; i += 2) all0 &= (w[i] == 0u);
        g_is64 = all0;
        int z = (cb2[0] == 0.f);
        for (int i = 0; i < 64; i++) z &= (cw2[i] == 0.f);
        g_skip_coord = z;
    }
}

__global__ void zero_kernel(int n) {
    int i = blockIdx.x * blockDim.x + threadIdx.x;
    if (i < n * 128) g_agg[i] = 0.f;
    if (i < n * 3)   g_delta[i] = 0.f;
    if (i < n)       g_deg[i] = 0.f;
}

// build bf16 hi/lo images of B = ew2^T, row-major [n=128][k=128]
__global__ void build_b_kernel(const float* __restrict__ ew2) {
    int idx = blockIdx.x * 256 + threadIdx.x;   // 0..16383
    int j = idx >> 7, k = idx & 127;            // B[j][k] = ew2[k][j]
    float v = ew2[k * 128 + j];
    __nv_bfloat16 hi = __float2bfloat16_rn(v);
    __nv_bfloat16 lo = __float2bfloat16_rn(v - __bfloat162float(hi));
    g_Bhi[j * 128 + k] = __bfloat16_as_ushort(hi);
    g_Blo[j * 128 + k] = __bfloat16_as_ushort(lo);
}

// ---------------- projection kernel: P1 = h@W_d + b1, P2 = h@W_s ------------
#define PROJ_SMEM_BYTES (64*132*4)

__global__ __launch_bounds__(256, 2) void proj_kernel(
    const float* __restrict__ h,
    const float* __restrict__ ew1, const float* __restrict__ eb1, int N)
{
    float* s_h = (float*)smem_raw;  // [64][132]
    const int tid = threadIdx.x;
    const int n0  = blockIdx.x * 64;

    for (int i = tid; i < 64 * 32; i += 256) {
        int e = i >> 5, c = i & 31;
        int n = n0 + e;
        float4 v = make_float4(0.f, 0.f, 0.f, 0.f);
        if (n < N) v = ((const float4*)h)[(size_t)n * 32 + c];
        *(float4*)(s_h + e * 132 + c * 4) = v;
    }
    __syncthreads();

    const int jg = tid & 31;
    const int eg = tid >> 5;
    const float* sA = s_h + eg * 8 * 132;

    float4 accP[8], accQ[8];
#pragma unroll
    for (int e = 0; e < 8; e++) {
        accP[e] = make_float4(0.f, 0.f, 0.f, 0.f);
        accQ[e] = make_float4(0.f, 0.f, 0.f, 0.f);
    }
    const float4* Wd = (const float4*)ew1;
    const float4* Ws = (const float4*)(ew1 + 128 * 128);
#pragma unroll 2
    for (int k4 = 0; k4 < 32; k4++) {
        const int kb = k4 * 4;
        float4 d0 = __ldg(Wd + (kb + 0) * 32 + jg);
        float4 d1 = __ldg(Wd + (kb + 1) * 32 + jg);
        float4 d2 = __ldg(Wd + (kb + 2) * 32 + jg);
        float4 d3 = __ldg(Wd + (kb + 3) * 32 + jg);
        float4 s0 = __ldg(Ws + (kb + 0) * 32 + jg);
        float4 s1 = __ldg(Ws + (kb + 1) * 32 + jg);
        float4 s2 = __ldg(Ws + (kb + 2) * 32 + jg);
        float4 s3 = __ldg(Ws + (kb + 3) * 32 + jg);
#pragma unroll
        for (int e = 0; e < 8; e++) {
            float4 a = *(const float4*)(sA + e * 132 + kb);
            accP[e].x = fmaf(a.x,d0.x,fmaf(a.y,d1.x,fmaf(a.z,d2.x,fmaf(a.w,d3.x,accP[e].x))));
            accP[e].y = fmaf(a.x,d0.y,fmaf(a.y,d1.y,fmaf(a.z,d2.y,fmaf(a.w,d3.y,accP[e].y))));
            accP[e].z = fmaf(a.x,d0.z,fmaf(a.y,d1.z,fmaf(a.z,d2.z,fmaf(a.w,d3.z,accP[e].z))));
            accP[e].w = fmaf(a.x,d0.w,fmaf(a.y,d1.w,fmaf(a.z,d2.w,fmaf(a.w,d3.w,accP[e].w))));
            accQ[e].x = fmaf(a.x,s0.x,fmaf(a.y,s1.x,fmaf(a.z,s2.x,fmaf(a.w,s3.x,accQ[e].x))));
            accQ[e].y = fmaf(a.x,s0.y,fmaf(a.y,s1.y,fmaf(a.z,s2.y,fmaf(a.w,s3.y,accQ[e].y))));
            accQ[e].z = fmaf(a.x,s0.z,fmaf(a.y,s1.z,fmaf(a.z,s2.z,fmaf(a.w,s3.z,accQ[e].z))));
            accQ[e].w = fmaf(a.x,s0.w,fmaf(a.y,s1.w,fmaf(a.z,s2.w,fmaf(a.w,s3.w,accQ[e].w))));
        }
    }
    float4 b1 = __ldg((const float4*)eb1 + jg);
#pragma unroll
    for (int e = 0; e < 8; e++) {
        int n = n0 + eg * 8 + e;
        if (n < N) {
            float4 p = accP[e];
            p.x += b1.x; p.y += b1.y; p.z += b1.z; p.w += b1.w;
            ((float4*)g_P1)[(size_t)n * 32 + jg] = p;
            ((float4*)g_P2)[(size_t)n * 32 + jg] = accQ[e];
        }
    }
}

// ---------------- HMMA edge kernel ------------------------------------------
// 128 edges/block, 256 threads (8 warps), 1 CTA/SM.
// bf16 tiles use pitch 136 elems (272 B) -> ldmatrix row addresses hit banks
// 0,4,8,...,28: conflict-free.
#define APITCH  136
#define AROWB   272                  // bytes per row
#define TILE_B  (128 * AROWB)        // 34816 bytes per bf16 tile

#define EK_DST   0                   // int[128]
#define EK_SRC   512
#define EK_DSQ   1024                // float[128]
#define EK_DIST  1536
#define EK_REL   2048                // float[128][3]
#define EK_EA    3584                // float[128][4]
#define EK_TAIL  5632                // float[5][128]
#define EK_EB2   8192                // float[128]
#define EK_AHI   8704
#define EK_ALO   (EK_AHI + TILE_B)
#define EK_BHI   (EK_ALO + TILE_B)
#define EK_BLO   (EK_BHI + TILE_B)
#define EK_MSG   EK_AHI              // fp32 [128][128] reuses A tiles after MMA
#define EDGE_SMEM_BYTES (EK_BLO + TILE_B)   // 147968

__global__ __launch_bounds__(256, 1) void edge_tc_kernel(
    const float* __restrict__ x,
    const void*  __restrict__ eidx, const float* __restrict__ eattr,
    const float* __restrict__ ew1, const float* __restrict__ eb2,
    const float* __restrict__ cw1, const float* __restrict__ cb1,
    const float* __restrict__ cw2, const float* __restrict__ cb2,
    int E)
{
    char* smem = smem_raw;
    const uint32_t sb = (uint32_t)__cvta_generic_to_shared(smem);
    int*   s_dst  = (int*)(smem + EK_DST);
    int*   s_src  = (int*)(smem + EK_SRC);
    float* s_dsq  = (float*)(smem + EK_DSQ);
    float* s_dist = (float*)(smem + EK_DIST);
    float* s_rel  = (float*)(smem + EK_REL);
    float* s_ea   = (float*)(smem + EK_EA);
    float* s_tail = (float*)(smem + EK_TAIL);
    float* s_eb2  = (float*)(smem + EK_EB2);

    const int tid  = threadIdx.x;
    const int wid  = tid >> 5;
    const int lane = tid & 31;
    const int e0   = blockIdx.x * 128;

    // ---- stage 1: per-edge scalars ----
    if (tid < 128) {
        int ge = e0 + tid;
        int dI = -1, sI = 0;
        float rx = 0.f, ry = 0.f, rz = 0.f, dsq = 1e-8f;
        float4 ea = make_float4(0.f, 0.f, 0.f, 0.f);
        if (ge < E) {
            if (g_is64) {
                const long long* p = (const long long*)eidx;
                sI = (int)p[ge]; dI = (int)p[E + ge];
            } else {
                const int* p = (const int*)eidx;
                sI = p[ge]; dI = p[E + ge];
            }
            const float* xd = x + (size_t)dI * 3;
            const float* xs = x + (size_t)sI * 3;
            rx = xd[0] - xs[0]; ry = xd[1] - xs[1]; rz = xd[2] - xs[2];
            dsq = fmaxf(rx * rx + ry * ry + rz * rz, 1e-8f);
            ea = ((const float4*)eattr)[ge];
        }
        s_dst[tid] = dI; s_src[tid] = sI;
        s_rel[tid * 3 + 0] = rx; s_rel[tid * 3 + 1] = ry; s_rel[tid * 3 + 2] = rz;
        s_dist[tid] = sqrtf(dsq);
        s_dsq[tid]  = dsq;
        *(float4*)(s_ea + tid * 4) = ea;
    }
    // tail weights (rows 256..260 of ew1)
    if (tid < 160) {
        int r = tid >> 5, c = tid & 31;
        *(float4*)(s_tail + r * 128 + c * 4) =
            __ldg((const float4*)(ew1 + (256 + r) * 128) + c);
    }
    if (tid >= 160 && tid < 192)
        *(float4*)(s_eb2 + (tid - 160) * 4) = __ldg((const float4*)eb2 + (tid - 160));
    // copy B hi/lo images into padded SMEM tiles
    for (int i = tid; i < 128 * 16; i += 256) {
        int rw = i >> 4, c = i & 15;
        *(uint4*)(smem + EK_BHI + rw * AROWB + c * 16) = ((const uint4*)g_Bhi)[rw * 16 + c];
        *(uint4*)(smem + EK_BLO + rw * AROWB + c * 16) = ((const uint4*)g_Blo)[rw * 16 + c];
    }
    __syncthreads();

    // ---- stage 2: gather + tail + silu -> bf16 hi/lo A tiles ----
    // warp w handles edges w*16 .. w*16+15; lane covers 4 channels
#pragma unroll 4
    for (int it = 0; it < 16; it++) {
        int e  = wid * 16 + it;
        int dI = s_dst[e];
        float4 v = make_float4(0.f, 0.f, 0.f, 0.f);
        if (dI >= 0) {
            float4 a = __ldg((const float4*)g_P1 + (size_t)dI * 32 + lane);
            float4 b = __ldg((const float4*)g_P2 + (size_t)s_src[e] * 32 + lane);
            float ds = s_dsq[e];
            float4 ea = *(const float4*)(s_ea + e * 4);
            float4 wd = *(const float4*)(s_tail + 0 * 128 + lane * 4);
            float4 a0 = *(const float4*)(s_tail + 1 * 128 + lane * 4);
            float4 a1 = *(const float4*)(s_tail + 2 * 128 + lane * 4);
            float4 a2 = *(const float4*)(s_tail + 3 * 128 + lane * 4);
            float4 a3 = *(const float4*)(s_tail + 4 * 128 + lane * 4);
            v.x = a.x + b.x + fmaf(ds,wd.x,fmaf(ea.x,a0.x,fmaf(ea.y,a1.x,fmaf(ea.z,a2.x,ea.w*a3.x))));
            v.y = a.y + b.y + fmaf(ds,wd.y,fmaf(ea.x,a0.y,fmaf(ea.y,a1.y,fmaf(ea.z,a2.y,ea.w*a3.y))));
            v.z = a.z + b.z + fmaf(ds,wd.z,fmaf(ea.x,a0.z,fmaf(ea.y,a1.z,fmaf(ea.z,a2.z,ea.w*a3.z))));
            v.w = a.w + b.w + fmaf(ds,wd.w,fmaf(ea.x,a0.w,fmaf(ea.y,a1.w,fmaf(ea.z,a2.w,ea.w*a3.w))));
            v.x = silu_f(v.x); v.y = silu_f(v.y); v.z = silu_f(v.z); v.w = silu_f(v.w);
        }
        __nv_bfloat16 hx = __float2bfloat16_rn(v.x), hy = __float2bfloat16_rn(v.y);
        __nv_bfloat16 hz = __float2bfloat16_rn(v.z), hw = __float2bfloat16_rn(v.w);
        __nv_bfloat16 lx = __float2bfloat16_rn(v.x - __bfloat162float(hx));
        __nv_bfloat16 ly = __float2bfloat16_rn(v.y - __bfloat162float(hy));
        __nv_bfloat16 lz = __float2bfloat16_rn(v.z - __bfloat162float(hz));
        __nv_bfloat16 lw = __float2bfloat16_rn(v.w - __bfloat162float(hw));
        uint2 hi, lo;
        hi.x = (uint32_t)__bfloat16_as_ushort(hx) | ((uint32_t)__bfloat16_as_ushort(hy) << 16);
        hi.y = (uint32_t)__bfloat16_as_ushort(hz) | ((uint32_t)__bfloat16_as_ushort(hw) << 16);
        lo.x = (uint32_t)__bfloat16_as_ushort(lx) | ((uint32_t)__bfloat16_as_ushort(ly) << 16);
        lo.y = (uint32_t)__bfloat16_as_ushort(lz) | ((uint32_t)__bfloat16_as_ushort(lw) << 16);
        *(uint2*)(smem + EK_AHI + e * AROWB + lane * 8) = hi;
        *(uint2*)(smem + EK_ALO + e * AROWB + lane * 8) = lo;
    }
    __syncthreads();

    // ---- stage 3: 3-term bf16 HMMA, D[16 x 128] per warp ----
    float c[16][4];
#pragma unroll
    for (int nt = 0; nt < 16; nt++) {
        c[nt][0] = 0.f; c[nt][1] = 0.f; c[nt][2] = 0.f; c[nt][3] = 0.f;
    }
    {
        const int mi = lane >> 3, r = lane & 7;
        // A: mi0:(row r, k+0) mi1:(row 8+r, k+0) mi2:(row r, k+8) mi3:(row 8+r, k+8)
        const uint32_t a_base = sb + EK_AHI
            + (uint32_t)((wid * 16 + (mi & 1) * 8 + r) * APITCH + (mi >> 1) * 8) * 2u;
        // B: mi0:(n r, k+0) mi1:(n r, k+8) mi2:(n 8+r, k+0) mi3:(n 8+r, k+8)
        const uint32_t b_base = sb + EK_BHI
            + (uint32_t)(((mi >> 1) * 8 + r) * APITCH + (mi & 1) * 8) * 2u;

#pragma unroll
        for (int ks = 0; ks < 8; ks++) {
            uint32_t ah[4], al[4];
            uint32_t ka = a_base + ks * 32;          // k advances 16 bf16 = 32 B
            LDSM_X4(ah, ka);
            LDSM_X4(al, ka + TILE_B);
            uint32_t kb = b_base + ks * 32;
#pragma unroll
            for (int np = 0; np < 8; np++) {
                uint32_t bh[4], bl[4];
                LDSM_X4(bh, kb);
                LDSM_X4(bl, kb + TILE_B);
                mma16816(c[2*np],   ah, bh + 0);
                mma16816(c[2*np+1], ah, bh + 2);
                mma16816(c[2*np],   al, bh + 0);
                mma16816(c[2*np+1], al, bh + 2);
                mma16816(c[2*np],   ah, bl + 0);
                mma16816(c[2*np+1], ah, bl + 2);
                kb += 16 * AROWB;                    // next 16 n-rows
            }
        }
    }

    // ---- stage 4: bias + silu -> msg; v2 reductions into g_agg ----
    const int gid = lane >> 2, tig = lane & 3;
    const int row0 = wid * 16 + gid;                 // block-local edge rows
    const int row1 = row0 + 8;
    const int d0I = s_dst[row0], d1I = s_dst[row1];
    const int skip = g_skip_coord;

    float m0[16][2], m1[16][2];
#pragma unroll
    for (int nt = 0; nt < 16; nt++) {
        int col = nt * 8 + tig * 2;
        float b0 = s_eb2[col], b1 = s_eb2[col + 1];
        m0[nt][0] = silu_f(c[nt][0] + b0);
        m0[nt][1] = silu_f(c[nt][1] + b1);
        m1[nt][0] = silu_f(c[nt][2] + b0);
        m1[nt][1] = silu_f(c[nt][3] + b1);
    }
    if (d0I >= 0) {
        float* base = g_agg + (size_t)d0I * 128 + tig * 2;
#pragma unroll
        for (int nt = 0; nt < 16; nt++)
            red_add_v2(base + nt * 8, m0[nt][0], m0[nt][1]);
    }
    if (d1I >= 0) {
        float* base = g_agg + (size_t)d1I * 128 + tig * 2;
#pragma unroll
        for (int nt = 0; nt < 16; nt++)
            red_add_v2(base + nt * 8, m1[nt][0], m1[nt][1]);
    }

    if (skip) return;   // uniform: cw2==0 && cb2==0 => x_out == x

    // ---- fallback coord path: stage msg into SMEM, SIMT coord MLP ----
    __syncthreads();    // A tiles no longer needed
    {
        float* s_msg = (float*)(smem + EK_MSG);
#pragma unroll
        for (int nt = 0; nt < 16; nt++) {
            int col = nt * 8 + tig * 2;
            *(float2*)(s_msg + row0 * 128 + col) = make_float2(m0[nt][0], m0[nt][1]);
            *(float2*)(s_msg + row1 * 128 + col) = make_float2(m1[nt][0], m1[nt][1]);
        }
    }
    __syncthreads();
    {
        float* s_msg = (float*)(smem + EK_MSG);
        const int jc = tid & 15;
        const int ec = tid >> 4;   // 16 groups x 8 edges
        float4 acc3[8];
#pragma unroll
        for (int e = 0; e < 8; e++) acc3[e] = make_float4(0.f, 0.f, 0.f, 0.f);
        const float4* C1 = (const float4*)cw1;
        const float* sM = s_msg + ec * 8 * 128;
#pragma unroll 2
        for (int k4 = 0; k4 < 32; k4++) {
            const int kb = k4 * 4;
            float4 w0 = __ldg(C1 + (kb + 0) * 16 + jc);
            float4 w1 = __ldg(C1 + (kb + 1) * 16 + jc);
            float4 w2 = __ldg(C1 + (kb + 2) * 16 + jc);
            float4 w3 = __ldg(C1 + (kb + 3) * 16 + jc);
#pragma unroll
            for (int e = 0; e < 8; e++) {
                float4 a = *(const float4*)(sM + e * 128 + kb);
                acc3[e].x = fmaf(a.x,w0.x,fmaf(a.y,w1.x,fmaf(a.z,w2.x,fmaf(a.w,w3.x,acc3[e].x))));
                acc3[e].y = fmaf(a.x,w0.y,fmaf(a.y,w1.y,fmaf(a.z,w2.y,fmaf(a.w,w3.y,acc3[e].y))));
                acc3[e].z = fmaf(a.x,w0.z,fmaf(a.y,w1.z,fmaf(a.z,w2.z,fmaf(a.w,w3.z,acc3[e].z))));
                acc3[e].w = fmaf(a.x,w0.w,fmaf(a.y,w1.w,fmaf(a.z,w2.w,fmaf(a.w,w3.w,acc3[e].w))));
            }
        }
        float4 bc = __ldg((const float4*)cb1 + jc);
        float4 c2 = __ldg((const float4*)cw2 + jc);
        float part[8];
#pragma unroll
        for (int e = 0; e < 8; e++) {
            float cx = silu_f(acc3[e].x + bc.x);
            float cy = silu_f(acc3[e].y + bc.y);
            float cz = silu_f(acc3[e].z + bc.z);
            float cw_ = silu_f(acc3[e].w + bc.w);
            part[e] = cx * c2.x + cy * c2.y + cz * c2.z + cw_ * c2.w;
        }
#pragma unroll
        for (int off = 8; off > 0; off >>= 1) {
#pragma unroll
            for (int e = 0; e < 8; e++)
                part[e] += __shfl_xor_sync(0xffffffffu, part[e], off, 16);
        }
        if (jc == 0) {
            float cb2v = __ldg(cb2);
#pragma unroll
            for (int e = 0; e < 8; e++) {
                int ee = ec * 8 + e;
                int dI = s_dst[ee];
                if (dI >= 0) {
                    float wv = part[e] + cb2v;
                    float f = wv / (s_dist[ee] + 1.f);
                    atomicAdd(&g_delta[dI * 3 + 0], s_rel[ee * 3 + 0] * f);
                    atomicAdd(&g_delta[dI * 3 + 1], s_rel[ee * 3 + 1] * f);
                    atomicAdd(&g_delta[dI * 3 + 2], s_rel[ee * 3 + 2] * f);
                    atomicAdd(&g_deg[dI], 1.f);
                }
            }
        }
    }
}

// ---------------- node kernel: node MLP + residual + LayerNorm -------------
#define NODE_SMEM_BYTES ((64*256 + 64*132) * 4)

__global__ __launch_bounds__(256, 2) void node_kernel(
    const float* __restrict__ h,
    const float* __restrict__ nw1, const float* __restrict__ nb1,
    const float* __restrict__ nw2, const float* __restrict__ nb2,
    const float* __restrict__ ln_g, const float* __restrict__ ln_b,
    float* __restrict__ out, int N)
{
    float* smemf = (float*)smem_raw;
    float* s_in = smemf;             // [64][256] = [h | agg]
    float* s_t1 = smemf + 64 * 256;  // [64][132]
    const int tid = threadIdx.x;
    const int n0  = blockIdx.x * 64;

    for (int i = tid; i < 64 * 32; i += 256) {
        int e = i >> 5, c = i & 31;
        int n = n0 + e;
        float4 hv = make_float4(0.f, 0.f, 0.f, 0.f), av = hv;
        if (n < N) {
            hv = ((const float4*)h)[(size_t)n * 32 + c];
            av = ((const float4*)g_agg)[(size_t)n * 32 + c];
        }
        *(float4*)(s_in + e * 256 + c * 4) = hv;
        *(float4*)(s_in + e * 256 + 128 + c * 4) = av;
    }
    __syncthreads();

    const int jg = tid & 31;
    const int eg = tid >> 5;
    const float* sA = s_in + eg * 8 * 256;

    float4 acc[8];
#pragma unroll
    for (int e = 0; e < 8; e++) acc[e] = make_float4(0.f, 0.f, 0.f, 0.f);
    const float4* W1 = (const float4*)nw1;
#pragma unroll 2
    for (int k4 = 0; k4 < 64; k4++) {
        const int kb = k4 * 4;
        float4 w0 = __ldg(W1 + (kb + 0) * 32 + jg);
        float4 w1 = __ldg(W1 + (kb + 1) * 32 + jg);
        float4 w2 = __ldg(W1 + (kb + 2) * 32 + jg);
        float4 w3 = __ldg(W1 + (kb + 3) * 32 + jg);
#pragma unroll
        for (int e = 0; e < 8; e++) {
            float4 a = *(const float4*)(sA + e * 256 + kb);
            acc[e].x = fmaf(a.x,w0.x,fmaf(a.y,w1.x,fmaf(a.z,w2.x,fmaf(a.w,w3.x,acc[e].x))));
            acc[e].y = fmaf(a.x,w0.y,fmaf(a.y,w1.y,fmaf(a.z,w2.y,fmaf(a.w,w3.y,acc[e].y))));
            acc[e].z = fmaf(a.x,w0.z,fmaf(a.y,w1.z,fmaf(a.z,w2.z,fmaf(a.w,w3.z,acc[e].z))));
            acc[e].w = fmaf(a.x,w0.w,fmaf(a.y,w1.w,fmaf(a.z,w2.w,fmaf(a.w,w3.w,acc[e].w))));
        }
    }
    {
        float4 b1 = __ldg((const float4*)nb1 + jg);
#pragma unroll
        for (int e = 0; e < 8; e++) {
            float4 v;
            v.x = silu_f(acc[e].x + b1.x);
            v.y = silu_f(acc[e].y + b1.y);
            v.z = silu_f(acc[e].z + b1.z);
            v.w = silu_f(acc[e].w + b1.w);
            *(float4*)(s_t1 + (eg * 8 + e) * 132 + jg * 4) = v;
        }
    }
    __syncthreads();

#pragma unroll
    for (int e = 0; e < 8; e++) acc[e] = make_float4(0.f, 0.f, 0.f, 0.f);
    const float4* W2 = (const float4*)nw2;
    const float* sB = s_t1 + eg * 8 * 132;
#pragma unroll 2
    for (int k4 = 0; k4 < 32; k4++) {
        const int kb = k4 * 4;
        float4 w0 = __ldg(W2 + (kb + 0) * 32 + jg);
        float4 w1 = __ldg(W2 + (kb + 1) * 32 + jg);
        float4 w2 = __ldg(W2 + (kb + 2) * 32 + jg);
        float4 w3 = __ldg(W2 + (kb + 3) * 32 + jg);
#pragma unroll
        for (int e = 0; e < 8; e++) {
            float4 a = *(const float4*)(sB + e * 132 + kb);
            acc[e].x = fmaf(a.x,w0.x,fmaf(a.y,w1.x,fmaf(a.z,w2.x,fmaf(a.w,w3.x,acc[e].x))));
            acc[e].y = fmaf(a.x,w0.y,fmaf(a.y,w1.y,fmaf(a.z,w2.y,fmaf(a.w,w3.y,acc[e].y))));
            acc[e].z = fmaf(a.x,w0.z,fmaf(a.y,w1.z,fmaf(a.z,w2.z,fmaf(a.w,w3.z,acc[e].z))));
            acc[e].w = fmaf(a.x,w0.w,fmaf(a.y,w1.w,fmaf(a.z,w2.w,fmaf(a.w,w3.w,acc[e].w))));
        }
    }
    {
        float4 b2 = __ldg((const float4*)nb2 + jg);
        float4 g4 = __ldg((const float4*)ln_g + jg);
        float4 bb = __ldg((const float4*)ln_b + jg);
#pragma unroll
        for (int e = 0; e < 8; e++) {
            float4 r = *(const float4*)(sA + e * 256 + jg * 4);
            float4 o;
            o.x = acc[e].x + b2.x + r.x;
            o.y = acc[e].y + b2.y + r.y;
            o.z = acc[e].z + b2.z + r.z;
            o.w = acc[e].w + b2.w + r.w;
            float s = o.x + o.y + o.z + o.w;
#pragma unroll
            for (int off = 16; off > 0; off >>= 1)
                s += __shfl_xor_sync(0xffffffffu, s, off);
            float mean = s * (1.f / 128.f);
            float dx = o.x - mean, dy = o.y - mean, dz = o.z - mean, dw = o.w - mean;
            float q = dx * dx + dy * dy + dz * dz + dw * dw;
#pragma unroll
            for (int off = 16; off > 0; off >>= 1)
                q += __shfl_xor_sync(0xffffffffu, q, off);
            float inv = rsqrtf(q * (1.f / 128.f) + 1e-5f);
            float4 y;
            y.x = dx * inv * g4.x + bb.x;
            y.y = dy * inv * g4.y + bb.y;
            y.z = dz * inv * g4.z + bb.z;
            y.w = dw * inv * g4.w + bb.w;
            int n = n0 + eg * 8 + e;
            if (n < N) ((float4*)out)[(size_t)n * 32 + jg] = y;
        }
    }
}

// ---------------- x output -------------------------------------------------
__global__ void coord_out_kernel(const float* __restrict__ x,
                                 const float* __restrict__ logit,
                                 float* __restrict__ out_x, int N)
{
    int n = blockIdx.x * blockDim.x + threadIdx.x;
    if (n < N) {
        if (g_skip_coord) {
            out_x[n * 3 + 0] = x[n * 3 + 0];
            out_x[n * 3 + 1] = x[n * 3 + 1];
            out_x[n * 3 + 2] = x[n * 3 + 2];
        } else {
            float scale = 1.f / (1.f + expf(-logit[0]));
            float dg = fmaxf(g_deg[n], 1.f);
            float inv = scale / dg;
            out_x[n * 3 + 0] = x[n * 3 + 0] + g_delta[n * 3 + 0] * inv;
            out_x[n * 3 + 1] = x[n * 3 + 1] + g_delta[n * 3 + 1] * inv;
            out_x[n * 3 + 2] = x[n * 3 + 2] + g_delta[n * 3 + 2] * inv;
        }
    }
}

// ---------------- launcher --------------------------------------------------
extern "C" void kernel_launch(void* const* d_in, const int* in_sizes, int n_in,
                              void* d_out, int out_size)
{
    const float* h   = (const float*)d_in[0];
    const float* x   = (const float*)d_in[1];
    const void*  ei  = d_in[2];
    const float* ea  = (const float*)d_in[3];
    const float* ew1 = (const float*)d_in[4];
    const float* eb1 = (const float*)d_in[5];
    const float* ew2 = (const float*)d_in[6];
    const float* eb2 = (const float*)d_in[7];
    const float* nw1 = (const float*)d_in[8];
    const float* nb1 = (const float*)d_in[9];
    const float* nw2 = (const float*)d_in[10];
    const float* nb2 = (const float*)d_in[11];
    const float* cw1 = (const float*)d_in[12];
    const float* cb1 = (const float*)d_in[13];
    const float* cw2 = (const float*)d_in[14];
    const float* cb2 = (const float*)d_in[15];
    const float* lgt = (const float*)d_in[16];
    const float* lng = (const float*)d_in[17];
    const float* lnb = (const float*)d_in[18];

    const int N = in_sizes[0] / 128;
    const int E = in_sizes[3] / 4;

    float* out_h = (float*)d_out;
    float* out_x = out_h + (size_t)N * 128;

    cudaFuncSetAttribute(proj_kernel, cudaFuncAttributeMaxDynamicSharedMemorySize,
                         PROJ_SMEM_BYTES);
    cudaFuncSetAttribute(edge_tc_kernel, cudaFuncAttributeMaxDynamicSharedMemorySize,
                         EDGE_SMEM_BYTES);
    cudaFuncSetAttribute(node_kernel, cudaFuncAttributeMaxDynamicSharedMemorySize,
                         NODE_SMEM_BYTES);

    detect_kernel<<<1, 32>>>((const unsigned int*)ei, cw2, cb2);
    zero_kernel<<<(N * 128 + 255) / 256, 256>>>(N);
    build_b_kernel<<<64, 256>>>(ew2);
    proj_kernel<<<(N + 63) / 64, 256, PROJ_SMEM_BYTES>>>(h, ew1, eb1, N);
    edge_tc_kernel<<<(E + 127) / 128, 256, EDGE_SMEM_BYTES>>>(
        x, ei, ea, ew1, eb2, cw1, cb1, cw2, cb2, E);
    node_kernel<<<(N + 63) / 64, 256, NODE_SMEM_BYTES>>>(
        h, nw1, nb1, nw2, nb2, lng, lnb, out_h, N);
    coord_out_kernel<<<(N + 255) / 256, 256>>>(x, lgt, out_x, N);
}

// round 6
// speedup vs baseline: 3.8706x; 1.7723x over previous
#include <cuda_runtime.h>
#include <cuda_bf16.h>
#include <cuda_fp16.h>
#include <cstdint>

#define NMAX 50000

// single shared-memory symbol for all kernels (nvcc merges extern __shared__)
extern __shared__ __align__(1024) char smem_raw[];

// ---------------- scratch (static device arrays: allocation-free) ----------
__device__ float g_agg[NMAX * 128];
__device__ float g_P1[NMAX * 128];     // h @ ew1[0:128]   + eb1
__device__ float g_P2[NMAX * 128];     // h @ ew1[128:256]
__device__ float g_delta[NMAX * 3];
__device__ float g_deg[NMAX];
__device__ int   g_is64;
__device__ int   g_skip_coord;
// ew2^T in fp16, plain row-major [n][k]
__device__ __align__(16) unsigned short g_Bh[16384];

__device__ __forceinline__ float silu_f(float v) {
    return v / (1.f + __expf(-v));
}

// ---------------- ptx helpers ----------------------------------------------
#define LDSM_X4(r, addr) \
    asm volatile("ldmatrix.sync.aligned.m8n8.x4.shared.b16 {%0,%1,%2,%3}, [%4];" \
        : "=r"((r)[0]), "=r"((r)[1]), "=r"((r)[2]), "=r"((r)[3]) : "r"(addr))

__device__ __forceinline__ void mma16816(float* c, const uint32_t* a, const uint32_t* b) {
    asm volatile("mma.sync.aligned.m16n8k16.row.col.f32.f16.f16.f32 "
        "{%0,%1,%2,%3}, {%4,%5,%6,%7}, {%8,%9}, {%0,%1,%2,%3};"
        : "+f"(c[0]), "+f"(c[1]), "+f"(c[2]), "+f"(c[3])
        : "r"(a[0]), "r"(a[1]), "r"(a[2]), "r"(a[3]), "r"(b[0]), "r"(b[1]));
}

__device__ __forceinline__ void red_add_v2(float* p, float a, float b) {
    asm volatile("red.global.add.v2.f32 [%0], {%1, %2};"
        :: "l"(p), "f"(a), "f"(b) : "memory");
}

// ---------------- probes ----------------------------------------------------
__global__ void detect_kernel(const unsigned int* __restrict__ w,
                              const float* __restrict__ cw2,
                              const float* __restrict__ cb2) {
    if (threadIdx.x == 0) {
        int all0 = 1;
#pragma unroll
        for (int i = 1; i < 64; i += 2) all0 &= (w[i] == 0u);
        g_is64 = all0;
        int z = (cb2[0] == 0.f);
        for (int i = 0; i < 64; i++) z &= (cw2[i] == 0.f);
        g_skip_coord = z;
    }
}

__global__ void zero_kernel(int n) {
    int i = blockIdx.x * blockDim.x + threadIdx.x;
    if (i < n * 128) g_agg[i] = 0.f;
    if (i < n * 3)   g_delta[i] = 0.f;
    if (i < n)       g_deg[i] = 0.f;
}

// build fp16 image of B = ew2^T, row-major [n=128][k=128]
__global__ void build_b_kernel(const float* __restrict__ ew2) {
    int idx = blockIdx.x * 256 + threadIdx.x;   // 0..16383
    int j = idx >> 7, k = idx & 127;            // B[j][k] = ew2[k][j]
    __half v = __float2half_rn(ew2[k * 128 + j]);
    g_Bh[j * 128 + k] = __half_as_ushort(v);
}

// ---------------- projection kernel: P1 = h@W_d + b1, P2 = h@W_s ------------
#define PROJ_SMEM_BYTES (64*132*4)

__global__ __launch_bounds__(256, 2) void proj_kernel(
    const float* __restrict__ h,
    const float* __restrict__ ew1, const float* __restrict__ eb1, int N)
{
    float* s_h = (float*)smem_raw;  // [64][132]
    const int tid = threadIdx.x;
    const int n0  = blockIdx.x * 64;

    for (int i = tid; i < 64 * 32; i += 256) {
        int e = i >> 5, c = i & 31;
        int n = n0 + e;
        float4 v = make_float4(0.f, 0.f, 0.f, 0.f);
        if (n < N) v = ((const float4*)h)[(size_t)n * 32 + c];
        *(float4*)(s_h + e * 132 + c * 4) = v;
    }
    __syncthreads();

    const int jg = tid & 31;
    const int eg = tid >> 5;
    const float* sA = s_h + eg * 8 * 132;

    float4 accP[8], accQ[8];
#pragma unroll
    for (int e = 0; e < 8; e++) {
        accP[e] = make_float4(0.f, 0.f, 0.f, 0.f);
        accQ[e] = make_float4(0.f, 0.f, 0.f, 0.f);
    }
    const float4* Wd = (const float4*)ew1;
    const float4* Ws = (const float4*)(ew1 + 128 * 128);
#pragma unroll 2
    for (int k4 = 0; k4 < 32; k4++) {
        const int kb = k4 * 4;
        float4 d0 = __ldg(Wd + (kb + 0) * 32 + jg);
        float4 d1 = __ldg(Wd + (kb + 1) * 32 + jg);
        float4 d2 = __ldg(Wd + (kb + 2) * 32 + jg);
        float4 d3 = __ldg(Wd + (kb + 3) * 32 + jg);
        float4 s0 = __ldg(Ws + (kb + 0) * 32 + jg);
        float4 s1 = __ldg(Ws + (kb + 1) * 32 + jg);
        float4 s2 = __ldg(Ws + (kb + 2) * 32 + jg);
        float4 s3 = __ldg(Ws + (kb + 3) * 32 + jg);
#pragma unroll
        for (int e = 0; e < 8; e++) {
            float4 a = *(const float4*)(sA + e * 132 + kb);
            accP[e].x = fmaf(a.x,d0.x,fmaf(a.y,d1.x,fmaf(a.z,d2.x,fmaf(a.w,d3.x,accP[e].x))));
            accP[e].y = fmaf(a.x,d0.y,fmaf(a.y,d1.y,fmaf(a.z,d2.y,fmaf(a.w,d3.y,accP[e].y))));
            accP[e].z = fmaf(a.x,d0.z,fmaf(a.y,d1.z,fmaf(a.z,d2.z,fmaf(a.w,d3.z,accP[e].z))));
            accP[e].w = fmaf(a.x,d0.w,fmaf(a.y,d1.w,fmaf(a.z,d2.w,fmaf(a.w,d3.w,accP[e].w))));
            accQ[e].x = fmaf(a.x,s0.x,fmaf(a.y,s1.x,fmaf(a.z,s2.x,fmaf(a.w,s3.x,accQ[e].x))));
            accQ[e].y = fmaf(a.x,s0.y,fmaf(a.y,s1.y,fmaf(a.z,s2.y,fmaf(a.w,s3.y,accQ[e].y))));
            accQ[e].z = fmaf(a.x,s0.z,fmaf(a.y,s1.z,fmaf(a.z,s2.z,fmaf(a.w,s3.z,accQ[e].z))));
            accQ[e].w = fmaf(a.x,s0.w,fmaf(a.y,s1.w,fmaf(a.z,s2.w,fmaf(a.w,s3.w,accQ[e].w))));
        }
    }
    float4 b1 = __ldg((const float4*)eb1 + jg);
#pragma unroll
    for (int e = 0; e < 8; e++) {
        int n = n0 + eg * 8 + e;
        if (n < N) {
            float4 p = accP[e];
            p.x += b1.x; p.y += b1.y; p.z += b1.z; p.w += b1.w;
            ((float4*)g_P1)[(size_t)n * 32 + jg] = p;
            ((float4*)g_P2)[(size_t)n * 32 + jg] = accQ[e];
        }
    }
}

// ---------------- HMMA edge kernel ------------------------------------------
// 128 edges/block, 256 threads (8 warps), 2 CTAs/SM.
// fp16 tiles, pitch 136 elems (272 B) -> conflict-free ldmatrix.
// Warp grid: 4 M-warps x 2 N-warps; each warp: 32 edge rows x 64 out cols.
#define APITCH  136
#define AROWB   272                  // bytes per row
#define TILE_B  (128 * AROWB)        // 34816 bytes per fp16 tile

#define EK_DST   0                   // int[128]
#define EK_SRC   512
#define EK_DSQ   1024                // float[128]
#define EK_DIST  1536
#define EK_REL   2048                // float[128][3]
#define EK_EA    3584                // float[128][4]
#define EK_TAIL  5632                // float[5][128]
#define EK_EB2   8192                // float[128]
#define EK_A     8704
#define EK_B     (EK_A + TILE_B)     // 43520
#define EK_MSG   EK_A                // fp32 [128][128] reuses A+B after MMA
#define EDGE_SMEM_BYTES (EK_B + TILE_B)   // 78336

__global__ __launch_bounds__(256, 2) void edge_tc_kernel(
    const float* __restrict__ x,
    const void*  __restrict__ eidx, const float* __restrict__ eattr,
    const float* __restrict__ ew1, const float* __restrict__ eb2,
    const float* __restrict__ cw1, const float* __restrict__ cb1,
    const float* __restrict__ cw2, const float* __restrict__ cb2,
    int E)
{
    char* smem = smem_raw;
    const uint32_t sb = (uint32_t)__cvta_generic_to_shared(smem);
    int*   s_dst  = (int*)(smem + EK_DST);
    int*   s_src  = (int*)(smem + EK_SRC);
    float* s_dsq  = (float*)(smem + EK_DSQ);
    float* s_dist = (float*)(smem + EK_DIST);
    float* s_rel  = (float*)(smem + EK_REL);
    float* s_ea   = (float*)(smem + EK_EA);
    float* s_tail = (float*)(smem + EK_TAIL);
    float* s_eb2  = (float*)(smem + EK_EB2);

    const int tid  = threadIdx.x;
    const int wid  = tid >> 5;
    const int lane = tid & 31;
    const int e0   = blockIdx.x * 128;

    // ---- stage 1: per-edge scalars ----
    if (tid < 128) {
        int ge = e0 + tid;
        int dI = -1, sI = 0;
        float rx = 0.f, ry = 0.f, rz = 0.f, dsq = 1e-8f;
        float4 ea = make_float4(0.f, 0.f, 0.f, 0.f);
        if (ge < E) {
            if (g_is64) {
                const long long* p = (const long long*)eidx;
                sI = (int)p[ge]; dI = (int)p[E + ge];
            } else {
                const int* p = (const int*)eidx;
                sI = p[ge]; dI = p[E + ge];
            }
            const float* xd = x + (size_t)dI * 3;
            const float* xs = x + (size_t)sI * 3;
            rx = xd[0] - xs[0]; ry = xd[1] - xs[1]; rz = xd[2] - xs[2];
            dsq = fmaxf(rx * rx + ry * ry + rz * rz, 1e-8f);
            ea = ((const float4*)eattr)[ge];
        }
        s_dst[tid] = dI; s_src[tid] = sI;
        s_rel[tid * 3 + 0] = rx; s_rel[tid * 3 + 1] = ry; s_rel[tid * 3 + 2] = rz;
        s_dist[tid] = sqrtf(dsq);
        s_dsq[tid]  = dsq;
        *(float4*)(s_ea + tid * 4) = ea;
    }
    // tail weights (rows 256..260 of ew1)
    if (tid < 160) {
        int r = tid >> 5, c = tid & 31;
        *(float4*)(s_tail + r * 128 + c * 4) =
            __ldg((const float4*)(ew1 + (256 + r) * 128) + c);
    }
    if (tid >= 160 && tid < 192)
        *(float4*)(s_eb2 + (tid - 160) * 4) = __ldg((const float4*)eb2 + (tid - 160));
    // copy B fp16 image into padded SMEM tile
    for (int i = tid; i < 128 * 16; i += 256) {
        int rw = i >> 4, c = i & 15;
        *(uint4*)(smem + EK_B + rw * AROWB + c * 16) = ((const uint4*)g_Bh)[rw * 16 + c];
    }
    __syncthreads();

    // ---- stage 2: gather + tail + silu -> fp16 A tile ----
#pragma unroll 4
    for (int it = 0; it < 16; it++) {
        int e  = wid * 16 + it;
        int dI = s_dst[e];
        float4 v = make_float4(0.f, 0.f, 0.f, 0.f);
        if (dI >= 0) {
            float4 a = __ldg((const float4*)g_P1 + (size_t)dI * 32 + lane);
            float4 b = __ldg((const float4*)g_P2 + (size_t)s_src[e] * 32 + lane);
            float ds = s_dsq[e];
            float4 ea = *(const float4*)(s_ea + e * 4);
            float4 wd = *(const float4*)(s_tail + 0 * 128 + lane * 4);
            float4 a0 = *(const float4*)(s_tail + 1 * 128 + lane * 4);
            float4 a1 = *(const float4*)(s_tail + 2 * 128 + lane * 4);
            float4 a2 = *(const float4*)(s_tail + 3 * 128 + lane * 4);
            float4 a3 = *(const float4*)(s_tail + 4 * 128 + lane * 4);
            v.x = a.x + b.x + fmaf(ds,wd.x,fmaf(ea.x,a0.x,fmaf(ea.y,a1.x,fmaf(ea.z,a2.x,ea.w*a3.x))));
            v.y = a.y + b.y + fmaf(ds,wd.y,fmaf(ea.x,a0.y,fmaf(ea.y,a1.y,fmaf(ea.z,a2.y,ea.w*a3.y))));
            v.z = a.z + b.z + fmaf(ds,wd.z,fmaf(ea.x,a0.z,fmaf(ea.y,a1.z,fmaf(ea.z,a2.z,ea.w*a3.z))));
            v.w = a.w + b.w + fmaf(ds,wd.w,fmaf(ea.x,a0.w,fmaf(ea.y,a1.w,fmaf(ea.z,a2.w,ea.w*a3.w))));
            v.x = silu_f(v.x); v.y = silu_f(v.y); v.z = silu_f(v.z); v.w = silu_f(v.w);
        }
        __half2 h01 = __floats2half2_rn(v.x, v.y);
        __half2 h23 = __floats2half2_rn(v.z, v.w);
        uint2 u;
        u.x = *(uint32_t*)&h01;
        u.y = *(uint32_t*)&h23;
        *(uint2*)(smem + EK_A + e * AROWB + lane * 8) = u;
    }
    __syncthreads();

    // ---- stage 3: fp16 HMMA, each warp D[32 x 64] ----
    const int mw = wid & 3;            // M quarter (rows mw*32..+31)
    const int nw = wid >> 2;           // N half  (cols nw*64..+63)
    float c[2][8][4];
#pragma unroll
    for (int mt = 0; mt < 2; mt++)
#pragma unroll
        for (int nt = 0; nt < 8; nt++) {
            c[mt][nt][0] = 0.f; c[mt][nt][1] = 0.f;
            c[mt][nt][2] = 0.f; c[mt][nt][3] = 0.f;
        }
    {
        const int mi = lane >> 3, r = lane & 7;
        uint32_t aBase0 = sb + EK_A
            + (uint32_t)((mw * 32 + 0  + (mi & 1) * 8 + r) * APITCH + (mi >> 1) * 8) * 2u;
        uint32_t aBase1 = sb + EK_A
            + (uint32_t)((mw * 32 + 16 + (mi & 1) * 8 + r) * APITCH + (mi >> 1) * 8) * 2u;
        uint32_t bBase = sb + EK_B
            + (uint32_t)((nw * 64 + (mi >> 1) * 8 + r) * APITCH + (mi & 1) * 8) * 2u;

#pragma unroll
        for (int ks = 0; ks < 8; ks++) {
            uint32_t af0[4], af1[4];
            LDSM_X4(af0, aBase0 + ks * 32);
            LDSM_X4(af1, aBase1 + ks * 32);
            uint32_t kb = bBase + ks * 32;
#pragma unroll
            for (int np = 0; np < 4; np++) {
                uint32_t bf[4];
                LDSM_X4(bf, kb);
                mma16816(c[0][2*np],   af0, bf + 0);
                mma16816(c[0][2*np+1], af0, bf + 2);
                mma16816(c[1][2*np],   af1, bf + 0);
                mma16816(c[1][2*np+1], af1, bf + 2);
                kb += 16 * AROWB;
            }
        }
    }

    // ---- stage 4: bias + silu, v2 reductions into g_agg (inline, no arrays)
    const int gid = lane >> 2, tig = lane & 3;
    const int skip = g_skip_coord;
#pragma unroll
    for (int mt = 0; mt < 2; mt++) {
        int rA = mw * 32 + mt * 16 + gid;
        int rB = rA + 8;
        int dA = s_dst[rA], dB = s_dst[rB];
        float* baseA = g_agg + (size_t)(dA < 0 ? 0 : dA) * 128 + nw * 64 + tig * 2;
        float* baseB = g_agg + (size_t)(dB < 0 ? 0 : dB) * 128 + nw * 64 + tig * 2;
#pragma unroll
        for (int nt = 0; nt < 8; nt++) {
            int col = nw * 64 + nt * 8 + tig * 2;
            float b0 = s_eb2[col], b1 = s_eb2[col + 1];
            if (dA >= 0)
                red_add_v2(baseA + nt * 8,
                           silu_f(c[mt][nt][0] + b0), silu_f(c[mt][nt][1] + b1));
            if (dB >= 0)
                red_add_v2(baseB + nt * 8,
                           silu_f(c[mt][nt][2] + b0), silu_f(c[mt][nt][3] + b1));
        }
    }

    if (skip) return;   // uniform: cw2==0 && cb2==0 => x_out == x

    // ---- fallback coord path: stage msg into SMEM (recompute), SIMT MLP ----
    __syncthreads();    // all warps done reading A/B tiles
    {
        float* s_msg = (float*)(smem + EK_MSG);
#pragma unroll
        for (int mt = 0; mt < 2; mt++) {
            int rA = mw * 32 + mt * 16 + gid;
            int rB = rA + 8;
#pragma unroll
            for (int nt = 0; nt < 8; nt++) {
                int col = nw * 64 + nt * 8 + tig * 2;
                float b0 = s_eb2[col], b1 = s_eb2[col + 1];
                *(float2*)(s_msg + rA * 128 + col) =
                    make_float2(silu_f(c[mt][nt][0] + b0), silu_f(c[mt][nt][1] + b1));
                *(float2*)(s_msg + rB * 128 + col) =
                    make_float2(silu_f(c[mt][nt][2] + b0), silu_f(c[mt][nt][3] + b1));
            }
        }
    }
    __syncthreads();
    {
        float* s_msg = (float*)(smem + EK_MSG);
        const int jc = tid & 15;
        const int ec = tid >> 4;   // 16 groups x 8 edges
        float4 acc3[8];
#pragma unroll
        for (int e = 0; e < 8; e++) acc3[e] = make_float4(0.f, 0.f, 0.f, 0.f);
        const float4* C1 = (const float4*)cw1;
        const float* sM = s_msg + ec * 8 * 128;
#pragma unroll 2
        for (int k4 = 0; k4 < 32; k4++) {
            const int kb = k4 * 4;
            float4 w0 = __ldg(C1 + (kb + 0) * 16 + jc);
            float4 w1 = __ldg(C1 + (kb + 1) * 16 + jc);
            float4 w2 = __ldg(C1 + (kb + 2) * 16 + jc);
            float4 w3 = __ldg(C1 + (kb + 3) * 16 + jc);
#pragma unroll
            for (int e = 0; e < 8; e++) {
                float4 a = *(const float4*)(sM + e * 128 + kb);
                acc3[e].x = fmaf(a.x,w0.x,fmaf(a.y,w1.x,fmaf(a.z,w2.x,fmaf(a.w,w3.x,acc3[e].x))));
                acc3[e].y = fmaf(a.x,w0.y,fmaf(a.y,w1.y,fmaf(a.z,w2.y,fmaf(a.w,w3.y,acc3[e].y))));
                acc3[e].z = fmaf(a.x,w0.z,fmaf(a.y,w1.z,fmaf(a.z,w2.z,fmaf(a.w,w3.z,acc3[e].z))));
                acc3[e].w = fmaf(a.x,w0.w,fmaf(a.y,w1.w,fmaf(a.z,w2.w,fmaf(a.w,w3.w,acc3[e].w))));
            }
        }
        float4 bc = __ldg((const float4*)cb1 + jc);
        float4 c2 = __ldg((const float4*)cw2 + jc);
        float part[8];
#pragma unroll
        for (int e = 0; e < 8; e++) {
            float cx = silu_f(acc3[e].x + bc.x);
            float cy = silu_f(acc3[e].y + bc.y);
            float cz = silu_f(acc3[e].z + bc.z);
            float cw_ = silu_f(acc3[e].w + bc.w);
            part[e] = cx * c2.x + cy * c2.y + cz * c2.z + cw_ * c2.w;
        }
#pragma unroll
        for (int off = 8; off > 0; off >>= 1) {
#pragma unroll
            for (int e = 0; e < 8; e++)
                part[e] += __shfl_xor_sync(0xffffffffu, part[e], off, 16);
        }
        if (jc == 0) {
            float cb2v = __ldg(cb2);
#pragma unroll
            for (int e = 0; e < 8; e++) {
                int ee = ec * 8 + e;
                int dI = s_dst[ee];
                if (dI >= 0) {
                    float wv = part[e] + cb2v;
                    float f = wv / (s_dist[ee] + 1.f);
                    atomicAdd(&g_delta[dI * 3 + 0], s_rel[ee * 3 + 0] * f);
                    atomicAdd(&g_delta[dI * 3 + 1], s_rel[ee * 3 + 1] * f);
                    atomicAdd(&g_delta[dI * 3 + 2], s_rel[ee * 3 + 2] * f);
                    atomicAdd(&g_deg[dI], 1.f);
                }
            }
        }
    }
}

// ---------------- node kernel: node MLP + residual + LayerNorm -------------
#define NODE_SMEM_BYTES ((64*256 + 64*132) * 4)

__global__ __launch_bounds__(256, 2) void node_kernel(
    const float* __restrict__ h,
    const float* __restrict__ nw1, const float* __restrict__ nb1,
    const float* __restrict__ nw2, const float* __restrict__ nb2,
    const float* __restrict__ ln_g, const float* __restrict__ ln_b,
    float* __restrict__ out, int N)
{
    float* smemf = (float*)smem_raw;
    float* s_in = smemf;             // [64][256] = [h | agg]
    float* s_t1 = smemf + 64 * 256;  // [64][132]
    const int tid = threadIdx.x;
    const int n0  = blockIdx.x * 64;

    for (int i = tid; i < 64 * 32; i += 256) {
        int e = i >> 5, c = i & 31;
        int n = n0 + e;
        float4 hv = make_float4(0.f, 0.f, 0.f, 0.f), av = hv;
        if (n < N) {
            hv = ((const float4*)h)[(size_t)n * 32 + c];
            av = ((const float4*)g_agg)[(size_t)n * 32 + c];
        }
        *(float4*)(s_in + e * 256 + c * 4) = hv;
        *(float4*)(s_in + e * 256 + 128 + c * 4) = av;
    }
    __syncthreads();

    const int jg = tid & 31;
    const int eg = tid >> 5;
    const float* sA = s_in + eg * 8 * 256;

    float4 acc[8];
#pragma unroll
    for (int e = 0; e < 8; e++) acc[e] = make_float4(0.f, 0.f, 0.f, 0.f);
    const float4* W1 = (const float4*)nw1;
#pragma unroll 2
    for (int k4 = 0; k4 < 64; k4++) {
        const int kb = k4 * 4;
        float4 w0 = __ldg(W1 + (kb + 0) * 32 + jg);
        float4 w1 = __ldg(W1 + (kb + 1) * 32 + jg);
        float4 w2 = __ldg(W1 + (kb + 2) * 32 + jg);
        float4 w3 = __ldg(W1 + (kb + 3) * 32 + jg);
#pragma unroll
        for (int e = 0; e < 8; e++) {
            float4 a = *(const float4*)(sA + e * 256 + kb);
            acc[e].x = fmaf(a.x,w0.x,fmaf(a.y,w1.x,fmaf(a.z,w2.x,fmaf(a.w,w3.x,acc[e].x))));
            acc[e].y = fmaf(a.x,w0.y,fmaf(a.y,w1.y,fmaf(a.z,w2.y,fmaf(a.w,w3.y,acc[e].y))));
            acc[e].z = fmaf(a.x,w0.z,fmaf(a.y,w1.z,fmaf(a.z,w2.z,fmaf(a.w,w3.z,acc[e].z))));
            acc[e].w = fmaf(a.x,w0.w,fmaf(a.y,w1.w,fmaf(a.z,w2.w,fmaf(a.w,w3.w,acc[e].w))));
        }
    }
    {
        float4 b1 = __ldg((const float4*)nb1 + jg);
#pragma unroll
        for (int e = 0; e < 8; e++) {
            float4 v;
            v.x = silu_f(acc[e].x + b1.x);
            v.y = silu_f(acc[e].y + b1.y);
            v.z = silu_f(acc[e].z + b1.z);
            v.w = silu_f(acc[e].w + b1.w);
            *(float4*)(s_t1 + (eg * 8 + e) * 132 + jg * 4) = v;
        }
    }
    __syncthreads();

#pragma unroll
    for (int e = 0; e < 8; e++) acc[e] = make_float4(0.f, 0.f, 0.f, 0.f);
    const float4* W2 = (const float4*)nw2;
    const float* sB = s_t1 + eg * 8 * 132;
#pragma unroll 2
    for (int k4 = 0; k4 < 32; k4++) {
        const int kb = k4 * 4;
        float4 w0 = __ldg(W2 + (kb + 0) * 32 + jg);
        float4 w1 = __ldg(W2 + (kb + 1) * 32 + jg);
        float4 w2 = __ldg(W2 + (kb + 2) * 32 + jg);
        float4 w3 = __ldg(W2 + (kb + 3) * 32 + jg);
#pragma unroll
        for (int e = 0; e < 8; e++) {
            float4 a = *(const float4*)(sB + e * 132 + kb);
            acc[e].x = fmaf(a.x,w0.x,fmaf(a.y,w1.x,fmaf(a.z,w2.x,fmaf(a.w,w3.x,acc[e].x))));
            acc[e].y = fmaf(a.x,w0.y,fmaf(a.y,w1.y,fmaf(a.z,w2.y,fmaf(a.w,w3.y,acc[e].y))));
            acc[e].z = fmaf(a.x,w0.z,fmaf(a.y,w1.z,fmaf(a.z,w2.z,fmaf(a.w,w3.z,acc[e].z))));
            acc[e].w = fmaf(a.x,w0.w,fmaf(a.y,w1.w,fmaf(a.z,w2.w,fmaf(a.w,w3.w,acc[e].w))));
        }
    }
    {
        float4 b2 = __ldg((const float4*)nb2 + jg);
        float4 g4 = __ldg((const float4*)ln_g + jg);
        float4 bb = __ldg((const float4*)ln_b + jg);
#pragma unroll
        for (int e = 0; e < 8; e++) {
            float4 r = *(const float4*)(sA + e * 256 + jg * 4);
            float4 o;
            o.x = acc[e].x + b2.x + r.x;
            o.y = acc[e].y + b2.y + r.y;
            o.z = acc[e].z + b2.z + r.z;
            o.w = acc[e].w + b2.w + r.w;
            float s = o.x + o.y + o.z + o.w;
#pragma unroll
            for (int off = 16; off > 0; off >>= 1)
                s += __shfl_xor_sync(0xffffffffu, s, off);
            float mean = s * (1.f / 128.f);
            float dx = o.x - mean, dy = o.y - mean, dz = o.z - mean, dw = o.w - mean;
            float q = dx * dx + dy * dy + dz * dz + dw * dw;
#pragma unroll
            for (int off = 16; off > 0; off >>= 1)
                q += __shfl_xor_sync(0xffffffffu, q, off);
            float inv = rsqrtf(q * (1.f / 128.f) + 1e-5f);
            float4 y;
            y.x = dx * inv * g4.x + bb.x;
            y.y = dy * inv * g4.y + bb.y;
            y.z = dz * inv * g4.z + bb.z;
            y.w = dw * inv * g4.w + bb.w;
            int n = n0 + eg * 8 + e;
            if (n < N) ((float4*)out)[(size_t)n * 32 + jg] = y;
        }
    }
}

// ---------------- x output -------------------------------------------------
__global__ void coord_out_kernel(const float* __restrict__ x,
                                 const float* __restrict__ logit,
                                 float* __restrict__ out_x, int N)
{
    int n = blockIdx.x * blockDim.x + threadIdx.x;
    if (n < N) {
        if (g_skip_coord) {
            out_x[n * 3 + 0] = x[n * 3 + 0];
            out_x[n * 3 + 1] = x[n * 3 + 1];
            out_x[n * 3 + 2] = x[n * 3 + 2];
        } else {
            float scale = 1.f / (1.f + expf(-logit[0]));
            float dg = fmaxf(g_deg[n], 1.f);
            float inv = scale / dg;
            out_x[n * 3 + 0] = x[n * 3 + 0] + g_delta[n * 3 + 0] * inv;
            out_x[n * 3 + 1] = x[n * 3 + 1] + g_delta[n * 3 + 1] * inv;
            out_x[n * 3 + 2] = x[n * 3 + 2] + g_delta[n * 3 + 2] * inv;
        }
    }
}

// ---------------- launcher --------------------------------------------------
extern "C" void kernel_launch(void* const* d_in, const int* in_sizes, int n_in,
                              void* d_out, int out_size)
{
    const float* h   = (const float*)d_in[0];
    const float* x   = (const float*)d_in[1];
    const void*  ei  = d_in[2];
    const float* ea  = (const float*)d_in[3];
    const float* ew1 = (const float*)d_in[4];
    const float* eb1 = (const float*)d_in[5];
    const float* ew2 = (const float*)d_in[6];
    const float* eb2 = (const float*)d_in[7];
    const float* nw1 = (const float*)d_in[8];
    const float* nb1 = (const float*)d_in[9];
    const float* nw2 = (const float*)d_in[10];
    const float* nb2 = (const float*)d_in[11];
    const float* cw1 = (const float*)d_in[12];
    const float* cb1 = (const float*)d_in[13];
    const float* cw2 = (const float*)d_in[14];
    const float* cb2 = (const float*)d_in[15];
    const float* lgt = (const float*)d_in[16];
    const float* lng = (const float*)d_in[17];
    const float* lnb = (const float*)d_in[18];

    const int N = in_sizes[0] / 128;
    const int E = in_sizes[3] / 4;

    float* out_h = (float*)d_out;
    float* out_x = out_h + (size_t)N * 128;

    cudaFuncSetAttribute(proj_kernel, cudaFuncAttributeMaxDynamicSharedMemorySize,
                         PROJ_SMEM_BYTES);
    cudaFuncSetAttribute(edge_tc_kernel, cudaFuncAttributeMaxDynamicSharedMemorySize,
                         EDGE_SMEM_BYTES);
    cudaFuncSetAttribute(node_kernel, cudaFuncAttributeMaxDynamicSharedMemorySize,
                         NODE_SMEM_BYTES);

    detect_kernel<<<1, 32>>>((const unsigned int*)ei, cw2, cb2);
    zero_kernel<<<(N * 128 + 255) / 256, 256>>>(N);
    build_b_kernel<<<64, 256>>>(ew2);
    proj_kernel<<<(N + 63) / 64, 256, PROJ_SMEM_BYTES>>>(h, ew1, eb1, N);
    edge_tc_kernel<<<(E + 127) / 128, 256, EDGE_SMEM_BYTES>>>(
        x, ei, ea, ew1, eb2, cw1, cb1, cw2, cb2, E);
    node_kernel<<<(N + 63) / 64, 256, NODE_SMEM_BYTES>>>(
        h, nw1, nb1, nw2, nb2, lng, lnb, out_h, N);
    coord_out_kernel<<<(N + 255) / 256, 256>>>(x, lgt, out_x, N);
}

// round 7
// speedup vs baseline: 5.0098x; 1.2943x over previous
#include <cuda_runtime.h>
#include <cuda_bf16.h>
#include <cuda_fp16.h>
#include <cstdint>

#define NMAX 50000

extern __shared__ __align__(1024) char smem_raw[];

// ---------------- scratch ----------------------------------------------------
__device__ float g_agg[NMAX * 128];
__device__ __align__(16) unsigned short g_P1h[NMAX * 128];  // fp16: h@W_d + eb1
__device__ __align__(16) unsigned short g_P2h[NMAX * 128];  // fp16: h@W_s
__device__ float g_delta[NMAX * 3];
__device__ float g_deg[NMAX];
__device__ int   g_is64;
__device__ int   g_skip_coord;
// fp16 weight images, row-major [out n][in k]
__device__ __align__(16) unsigned short g_Bh[16384];    // ew2^T
__device__ __align__(16) unsigned short g_Bd[16384];    // ew1[0:128]^T
__device__ __align__(16) unsigned short g_Bs[16384];    // ew1[128:256]^T
__device__ __align__(16) unsigned short g_Bn1[32768];   // nw1^T [128][256]
__device__ __align__(16) unsigned short g_Bn2[16384];   // nw2^T [128][128]

__device__ __forceinline__ float silu_f(float v) { return v / (1.f + __expf(-v)); }

// ---------------- ptx helpers ----------------------------------------------
#define LDSM_X4(r, addr) \
    asm volatile("ldmatrix.sync.aligned.m8n8.x4.shared.b16 {%0,%1,%2,%3}, [%4];" \
        : "=r"((r)[0]), "=r"((r)[1]), "=r"((r)[2]), "=r"((r)[3]) : "r"(addr))

__device__ __forceinline__ void mma16816(float* c, const uint32_t* a, const uint32_t* b) {
    asm volatile("mma.sync.aligned.m16n8k16.row.col.f32.f16.f16.f32 "
        "{%0,%1,%2,%3}, {%4,%5,%6,%7}, {%8,%9}, {%0,%1,%2,%3};"
        : "+f"(c[0]), "+f"(c[1]), "+f"(c[2]), "+f"(c[3])
        : "r"(a[0]), "r"(a[1]), "r"(a[2]), "r"(a[3]), "r"(b[0]), "r"(b[1]));
}

__device__ __forceinline__ void red_add_v4(float* p, float a, float b, float c, float d) {
    asm volatile("red.global.add.v4.f32 [%0], {%1, %2, %3, %4};"
        :: "l"(p), "f"(a), "f"(b), "f"(c), "f"(d) : "memory");
}

#define APITCH  136
#define AROWB   272
#define TILE_B  (128 * AROWB)        // 34816 bytes per fp16 tile

// ---------------- probes -----------------------------------------------------
__global__ void detect_kernel(const unsigned int* __restrict__ w,
                              const float* __restrict__ cw2,
                              const float* __restrict__ cb2) {
    if (threadIdx.x == 0) {
        int all0 = 1;
#pragma unroll
        for (int i = 1; i < 64; i += 2) all0 &= (w[i] == 0u);
        g_is64 = all0;
        int z = (cb2[0] == 0.f);
        for (int i = 0; i < 64; i++) z &= (cw2[i] == 0.f);
        g_skip_coord = z;
    }
}

__global__ void zero_kernel(int n) {
    int i = blockIdx.x * blockDim.x + threadIdx.x;
    if (i < n * 128) g_agg[i] = 0.f;
    if (i < n * 3)   g_delta[i] = 0.f;
    if (i < n)       g_deg[i] = 0.f;
}

// build all fp16 weight images
__global__ void build_b_kernel(const float* __restrict__ ew2,
                               const float* __restrict__ ew1,
                               const float* __restrict__ nw1,
                               const float* __restrict__ nw2) {
    int idx = blockIdx.x * 256 + threadIdx.x;   // 0..32767
    if (idx < 16384) {
        int j = idx >> 7, k = idx & 127;
        g_Bh[j * 128 + k] = __half_as_ushort(__float2half_rn(ew2[k * 128 + j]));
        g_Bd[j * 128 + k] = __half_as_ushort(__float2half_rn(ew1[k * 128 + j]));
        g_Bs[j * 128 + k] = __half_as_ushort(__float2half_rn(ew1[(128 + k) * 128 + j]));
        g_Bn2[j * 128 + k] = __half_as_ushort(__float2half_rn(nw2[k * 128 + j]));
    }
    {
        int j = idx >> 8, k = idx & 255;        // [128][256]
        g_Bn1[j * 256 + k] = __half_as_ushort(__float2half_rn(nw1[k * 128 + j]));
    }
}

// ---------------- HMMA proj kernel: P1h, P2h --------------------------------
#define PK_EB1  0
#define PK_A    1024
#define PK_BD   (PK_A + TILE_B)
#define PK_BS   (PK_BD + TILE_B)
#define PROJ_SMEM_BYTES (PK_BS + TILE_B)   // 105472

__global__ __launch_bounds__(256, 2) void proj_hmma(
    const float* __restrict__ h, const float* __restrict__ eb1, int N)
{
    char* smem = smem_raw;
    const uint32_t sb = (uint32_t)__cvta_generic_to_shared(smem);
    float* s_eb1 = (float*)(smem + PK_EB1);
    const int tid = threadIdx.x, wid = tid >> 5, lane = tid & 31;
    const int n0 = blockIdx.x * 128;

    if (tid < 32) *(float4*)(s_eb1 + tid * 4) = __ldg((const float4*)eb1 + tid);
    for (int i = tid; i < 128 * 16; i += 256) {
        int rw = i >> 4, c = i & 15;
        *(uint4*)(smem + PK_BD + rw * AROWB + c * 16) = ((const uint4*)g_Bd)[rw * 16 + c];
        *(uint4*)(smem + PK_BS + rw * AROWB + c * 16) = ((const uint4*)g_Bs)[rw * 16 + c];
    }
#pragma unroll 4
    for (int it = 0; it < 16; it++) {
        int row = wid * 16 + it;
        int n = n0 + row;
        float4 v = make_float4(0.f, 0.f, 0.f, 0.f);
        if (n < N) v = __ldg((const float4*)h + (size_t)n * 32 + lane);
        __half2 h01 = __floats2half2_rn(v.x, v.y);
        __half2 h23 = __floats2half2_rn(v.z, v.w);
        uint2 u; u.x = *(uint32_t*)&h01; u.y = *(uint32_t*)&h23;
        *(uint2*)(smem + PK_A + row * AROWB + lane * 8) = u;
    }
    __syncthreads();

    const int mw = wid & 3, nw = wid >> 2;
    const int mi = lane >> 3, r = lane & 7;
    const uint32_t aBase0 = sb + PK_A
        + (uint32_t)((mw * 32 + (mi & 1) * 8 + r) * APITCH + (mi >> 1) * 8) * 2u;
    const uint32_t aBase1 = aBase0 + 16 * AROWB;
    const uint32_t bBase = sb + PK_BD
        + (uint32_t)((nw * 64 + (mi >> 1) * 8 + r) * APITCH + (mi & 1) * 8) * 2u;
    const int gid = lane >> 2, tig = lane & 3;

    float c[2][8][4];
#pragma unroll
    for (int pass = 0; pass < 2; pass++) {
#pragma unroll
        for (int mt = 0; mt < 2; mt++)
#pragma unroll
            for (int nt = 0; nt < 8; nt++)
                c[mt][nt][0] = c[mt][nt][1] = c[mt][nt][2] = c[mt][nt][3] = 0.f;
        uint32_t bb = bBase + pass * (PK_BS - PK_BD);
#pragma unroll
        for (int ks = 0; ks < 8; ks++) {
            uint32_t af0[4], af1[4];
            LDSM_X4(af0, aBase0 + ks * 32);
            LDSM_X4(af1, aBase1 + ks * 32);
            uint32_t kb = bb + ks * 32;
#pragma unroll
            for (int np = 0; np < 4; np++) {
                uint32_t bf[4];
                LDSM_X4(bf, kb);
                mma16816(c[0][2*np],   af0, bf + 0);
                mma16816(c[0][2*np+1], af0, bf + 2);
                mma16816(c[1][2*np],   af1, bf + 0);
                mma16816(c[1][2*np+1], af1, bf + 2);
                kb += 16 * AROWB;
            }
        }
        unsigned short* dst = pass == 0 ? g_P1h : g_P2h;
#pragma unroll
        for (int mt = 0; mt < 2; mt++) {
            int rA = mw * 32 + mt * 16 + gid;
            int nA = n0 + rA, nB = nA + 8;
#pragma unroll
            for (int nt = 0; nt < 8; nt++) {
                int col = nw * 64 + nt * 8 + tig * 2;
                float b0 = pass == 0 ? s_eb1[col] : 0.f;
                float b1 = pass == 0 ? s_eb1[col + 1] : 0.f;
                if (nA < N) {
                    __half2 hv = __floats2half2_rn(c[mt][nt][0] + b0, c[mt][nt][1] + b1);
                    *(__half2*)(dst + (size_t)nA * 128 + col) = hv;
                }
                if (nB < N) {
                    __half2 hv = __floats2half2_rn(c[mt][nt][2] + b0, c[mt][nt][3] + b1);
                    *(__half2*)(dst + (size_t)nB * 128 + col) = hv;
                }
            }
        }
    }
}

// ---------------- HMMA edge kernel ------------------------------------------
#define EK_DST   0
#define EK_SRC   512
#define EK_DSQ   1024
#define EK_DIST  1536
#define EK_REL   2048
#define EK_EA    3584
#define EK_TAIL  5632
#define EK_EB2   8192
#define EK_A     8704
#define EK_B     (EK_A + TILE_B)
#define EK_MSG   EK_A
#define EDGE_SMEM_BYTES (EK_B + TILE_B)   // 78336

__global__ __launch_bounds__(256, 2) void edge_tc_kernel(
    const float* __restrict__ x,
    const void*  __restrict__ eidx, const float* __restrict__ eattr,
    const float* __restrict__ ew1, const float* __restrict__ eb2,
    const float* __restrict__ cw1, const float* __restrict__ cb1,
    const float* __restrict__ cw2, const float* __restrict__ cb2,
    int E)
{
    char* smem = smem_raw;
    const uint32_t sb = (uint32_t)__cvta_generic_to_shared(smem);
    int*   s_dst  = (int*)(smem + EK_DST);
    int*   s_src  = (int*)(smem + EK_SRC);
    float* s_dsq  = (float*)(smem + EK_DSQ);
    float* s_dist = (float*)(smem + EK_DIST);
    float* s_rel  = (float*)(smem + EK_REL);
    float* s_ea   = (float*)(smem + EK_EA);
    float* s_tail = (float*)(smem + EK_TAIL);
    float* s_eb2  = (float*)(smem + EK_EB2);

    const int tid  = threadIdx.x;
    const int wid  = tid >> 5;
    const int lane = tid & 31;
    const int e0   = blockIdx.x * 128;

    if (tid < 128) {
        int ge = e0 + tid;
        int dI = -1, sI = 0;
        float rx = 0.f, ry = 0.f, rz = 0.f, dsq = 1e-8f;
        float4 ea = make_float4(0.f, 0.f, 0.f, 0.f);
        if (ge < E) {
            if (g_is64) {
                const long long* p = (const long long*)eidx;
                sI = (int)p[ge]; dI = (int)p[E + ge];
            } else {
                const int* p = (const int*)eidx;
                sI = p[ge]; dI = p[E + ge];
            }
            const float* xd = x + (size_t)dI * 3;
            const float* xs = x + (size_t)sI * 3;
            rx = xd[0] - xs[0]; ry = xd[1] - xs[1]; rz = xd[2] - xs[2];
            dsq = fmaxf(rx * rx + ry * ry + rz * rz, 1e-8f);
            ea = ((const float4*)eattr)[ge];
        }
        s_dst[tid] = dI; s_src[tid] = sI;
        s_rel[tid * 3 + 0] = rx; s_rel[tid * 3 + 1] = ry; s_rel[tid * 3 + 2] = rz;
        s_dist[tid] = sqrtf(dsq);
        s_dsq[tid]  = dsq;
        *(float4*)(s_ea + tid * 4) = ea;
    }
    if (tid < 160) {
        int r = tid >> 5, c = tid & 31;
        *(float4*)(s_tail + r * 128 + c * 4) =
            __ldg((const float4*)(ew1 + (256 + r) * 128) + c);
    }
    if (tid >= 160 && tid < 192)
        *(float4*)(s_eb2 + (tid - 160) * 4) = __ldg((const float4*)eb2 + (tid - 160));
    for (int i = tid; i < 128 * 16; i += 256) {
        int rw = i >> 4, c = i & 15;
        *(uint4*)(smem + EK_B + rw * AROWB + c * 16) = ((const uint4*)g_Bh)[rw * 16 + c];
    }
    __syncthreads();

    // ---- gather fp16 P1/P2 + tail + silu -> fp16 A tile ----
#pragma unroll 4
    for (int it = 0; it < 16; it++) {
        int e  = wid * 16 + it;
        int dI = s_dst[e];
        float4 v = make_float4(0.f, 0.f, 0.f, 0.f);
        if (dI >= 0) {
            uint2 ua = *(const uint2*)(g_P1h + (size_t)dI * 128 + lane * 4);
            uint2 ub = *(const uint2*)(g_P2h + (size_t)s_src[e] * 128 + lane * 4);
            __half2 a01 = *(__half2*)&ua.x, a23 = *(__half2*)&ua.y;
            __half2 b01 = *(__half2*)&ub.x, b23 = *(__half2*)&ub.y;
            float ds = s_dsq[e];
            float4 ea = *(const float4*)(s_ea + e * 4);
            float4 wd = *(const float4*)(s_tail + 0 * 128 + lane * 4);
            float4 a0 = *(const float4*)(s_tail + 1 * 128 + lane * 4);
            float4 a1 = *(const float4*)(s_tail + 2 * 128 + lane * 4);
            float4 a2 = *(const float4*)(s_tail + 3 * 128 + lane * 4);
            float4 a3 = *(const float4*)(s_tail + 4 * 128 + lane * 4);
            v.x = __low2float(a01)  + __low2float(b01)
                + fmaf(ds,wd.x,fmaf(ea.x,a0.x,fmaf(ea.y,a1.x,fmaf(ea.z,a2.x,ea.w*a3.x))));
            v.y = __high2float(a01) + __high2float(b01)
                + fmaf(ds,wd.y,fmaf(ea.x,a0.y,fmaf(ea.y,a1.y,fmaf(ea.z,a2.y,ea.w*a3.y))));
            v.z = __low2float(a23)  + __low2float(b23)
                + fmaf(ds,wd.z,fmaf(ea.x,a0.z,fmaf(ea.y,a1.z,fmaf(ea.z,a2.z,ea.w*a3.z))));
            v.w = __high2float(a23) + __high2float(b23)
                + fmaf(ds,wd.w,fmaf(ea.x,a0.w,fmaf(ea.y,a1.w,fmaf(ea.z,a2.w,ea.w*a3.w))));
            v.x = silu_f(v.x); v.y = silu_f(v.y); v.z = silu_f(v.z); v.w = silu_f(v.w);
        }
        __half2 h01 = __floats2half2_rn(v.x, v.y);
        __half2 h23 = __floats2half2_rn(v.z, v.w);
        uint2 u; u.x = *(uint32_t*)&h01; u.y = *(uint32_t*)&h23;
        *(uint2*)(smem + EK_A + e * AROWB + lane * 8) = u;
    }
    __syncthreads();

    // ---- fp16 HMMA, each warp D[32 x 64] ----
    const int mw = wid & 3;
    const int nw = wid >> 2;
    float c[2][8][4];
#pragma unroll
    for (int mt = 0; mt < 2; mt++)
#pragma unroll
        for (int nt = 0; nt < 8; nt++)
            c[mt][nt][0] = c[mt][nt][1] = c[mt][nt][2] = c[mt][nt][3] = 0.f;
    {
        const int mi = lane >> 3, r = lane & 7;
        uint32_t aBase0 = sb + EK_A
            + (uint32_t)((mw * 32 + 0  + (mi & 1) * 8 + r) * APITCH + (mi >> 1) * 8) * 2u;
        uint32_t aBase1 = aBase0 + 16 * AROWB;
        uint32_t bBase = sb + EK_B
            + (uint32_t)((nw * 64 + (mi >> 1) * 8 + r) * APITCH + (mi & 1) * 8) * 2u;
#pragma unroll
        for (int ks = 0; ks < 8; ks++) {
            uint32_t af0[4], af1[4];
            LDSM_X4(af0, aBase0 + ks * 32);
            LDSM_X4(af1, aBase1 + ks * 32);
            uint32_t kb = bBase + ks * 32;
#pragma unroll
            for (int np = 0; np < 4; np++) {
                uint32_t bf[4];
                LDSM_X4(bf, kb);
                mma16816(c[0][2*np],   af0, bf + 0);
                mma16816(c[0][2*np+1], af0, bf + 2);
                mma16816(c[1][2*np],   af1, bf + 0);
                mma16816(c[1][2*np+1], af1, bf + 2);
                kb += 16 * AROWB;
            }
        }
    }

    // ---- bias + silu; pair-shuffle v4 reductions into g_agg ----
    const int gid = lane >> 2, tig = lane & 3;
    const int skip = g_skip_coord;
#pragma unroll
    for (int mt = 0; mt < 2; mt++) {
        int rA = mw * 32 + mt * 16 + gid;
        int rB = rA + 8;
        int dA = s_dst[rA], dB = s_dst[rB];
#pragma unroll
        for (int nt = 0; nt < 8; nt++) {
            int col = nw * 64 + nt * 8 + tig * 2;
            float b0 = s_eb2[col], b1 = s_eb2[col + 1];
            float mA0 = silu_f(c[mt][nt][0] + b0), mA1 = silu_f(c[mt][nt][1] + b1);
            float mB0 = silu_f(c[mt][nt][2] + b0), mB1 = silu_f(c[mt][nt][3] + b1);
            float pA0 = __shfl_down_sync(0xffffffffu, mA0, 1);
            float pA1 = __shfl_down_sync(0xffffffffu, mA1, 1);
            float pB0 = __shfl_down_sync(0xffffffffu, mB0, 1);
            float pB1 = __shfl_down_sync(0xffffffffu, mB1, 1);
            if ((tig & 1) == 0) {
                if (dA >= 0)
                    red_add_v4(g_agg + (size_t)dA * 128 + col, mA0, mA1, pA0, pA1);
                if (dB >= 0)
                    red_add_v4(g_agg + (size_t)dB * 128 + col, mB0, mB1, pB0, pB1);
            }
        }
    }

    if (skip) return;

    // ---- fallback coord path ----
    __syncthreads();
    {
        float* s_msg = (float*)(smem + EK_MSG);
#pragma unroll
        for (int mt = 0; mt < 2; mt++) {
            int rA = mw * 32 + mt * 16 + gid;
            int rB = rA + 8;
#pragma unroll
            for (int nt = 0; nt < 8; nt++) {
                int col = nw * 64 + nt * 8 + tig * 2;
                float b0 = s_eb2[col], b1 = s_eb2[col + 1];
                *(float2*)(s_msg + rA * 128 + col) =
                    make_float2(silu_f(c[mt][nt][0] + b0), silu_f(c[mt][nt][1] + b1));
                *(float2*)(s_msg + rB * 128 + col) =
                    make_float2(silu_f(c[mt][nt][2] + b0), silu_f(c[mt][nt][3] + b1));
            }
        }
    }
    __syncthreads();
    {
        float* s_msg = (float*)(smem + EK_MSG);
        const int jc = tid & 15;
        const int ec = tid >> 4;
        float4 acc3[8];
#pragma unroll
        for (int e = 0; e < 8; e++) acc3[e] = make_float4(0.f, 0.f, 0.f, 0.f);
        const float4* C1 = (const float4*)cw1;
        const float* sM = s_msg + ec * 8 * 128;
#pragma unroll 2
        for (int k4 = 0; k4 < 32; k4++) {
            const int kb = k4 * 4;
            float4 w0 = __ldg(C1 + (kb + 0) * 16 + jc);
            float4 w1 = __ldg(C1 + (kb + 1) * 16 + jc);
            float4 w2 = __ldg(C1 + (kb + 2) * 16 + jc);
            float4 w3 = __ldg(C1 + (kb + 3) * 16 + jc);
#pragma unroll
            for (int e = 0; e < 8; e++) {
                float4 a = *(const float4*)(sM + e * 128 + kb);
                acc3[e].x = fmaf(a.x,w0.x,fmaf(a.y,w1.x,fmaf(a.z,w2.x,fmaf(a.w,w3.x,acc3[e].x))));
                acc3[e].y = fmaf(a.x,w0.y,fmaf(a.y,w1.y,fmaf(a.z,w2.y,fmaf(a.w,w3.y,acc3[e].y))));
                acc3[e].z = fmaf(a.x,w0.z,fmaf(a.y,w1.z,fmaf(a.z,w2.z,fmaf(a.w,w3.z,acc3[e].z))));
                acc3[e].w = fmaf(a.x,w0.w,fmaf(a.y,w1.w,fmaf(a.z,w2.w,fmaf(a.w,w3.w,acc3[e].w))));
            }
        }
        float4 bc = __ldg((const float4*)cb1 + jc);
        float4 c2 = __ldg((const float4*)cw2 + jc);
        float part[8];
#pragma unroll
        for (int e = 0; e < 8; e++) {
            float cx = silu_f(acc3[e].x + bc.x);
            float cy = silu_f(acc3[e].y + bc.y);
            float cz = silu_f(acc3[e].z + bc.z);
            float cw_ = silu_f(acc3[e].w + bc.w);
            part[e] = cx * c2.x + cy * c2.y + cz * c2.z + cw_ * c2.w;
        }
#pragma unroll
        for (int off = 8; off > 0; off >>= 1) {
#pragma unroll
            for (int e = 0; e < 8; e++)
                part[e] += __shfl_xor_sync(0xffffffffu, part[e], off, 16);
        }
        if (jc == 0) {
            float cb2v = __ldg(cb2);
#pragma unroll
            for (int e = 0; e < 8; e++) {
                int ee = ec * 8 + e;
                int dI = s_dst[ee];
                if (dI >= 0) {
                    float wv = part[e] + cb2v;
                    float f = wv / (s_dist[ee] + 1.f);
                    atomicAdd(&g_delta[dI * 3 + 0], s_rel[ee * 3 + 0] * f);
                    atomicAdd(&g_delta[dI * 3 + 1], s_rel[ee * 3 + 1] * f);
                    atomicAdd(&g_delta[dI * 3 + 2], s_rel[ee * 3 + 2] * f);
                    atomicAdd(&g_deg[dI], 1.f);
                }
            }
        }
    }
}

// ---------------- HMMA node kernel ------------------------------------------
#define NK_NB1   0
#define NK_NB2   512
#define NK_LNG   1024
#define NK_LNB   1536
#define NK_A     2048
#define NK_B0    (NK_A + TILE_B)
#define NK_B1    (NK_B0 + TILE_B)
#define NK_O     2048                 // fp32 [128][132], reuses tiles after MMA
#define NODE_SMEM_BYTES (NK_B1 + TILE_B)   // 106496

__global__ __launch_bounds__(256, 2) void node_hmma(
    const float* __restrict__ h,
    const float* __restrict__ nb1, const float* __restrict__ nb2,
    const float* __restrict__ ln_g, const float* __restrict__ ln_b,
    float* __restrict__ out, int N)
{
    char* smem = smem_raw;
    const uint32_t sb = (uint32_t)__cvta_generic_to_shared(smem);
    float* s_nb1 = (float*)(smem + NK_NB1);
    float* s_nb2 = (float*)(smem + NK_NB2);
    float* s_lng = (float*)(smem + NK_LNG);
    float* s_lnb = (float*)(smem + NK_LNB);
    const int tid = threadIdx.x, wid = tid >> 5, lane = tid & 31;
    const int n0 = blockIdx.x * 128;

    if (tid < 32) {
        *(float4*)(s_nb1 + tid * 4) = __ldg((const float4*)nb1 + tid);
        *(float4*)(s_nb2 + tid * 4) = __ldg((const float4*)nb2 + tid);
        *(float4*)(s_lng + tid * 4) = __ldg((const float4*)ln_g + tid);
        *(float4*)(s_lnb + tid * 4) = __ldg((const float4*)ln_b + tid);
    }
    for (int i = tid; i < 128 * 16; i += 256) {
        int rw = i >> 4, c = i & 15;
        *(uint4*)(smem + NK_B0 + rw * AROWB + c * 16) = ((const uint4*)g_Bn1)[rw * 32 + c];
        *(uint4*)(smem + NK_B1 + rw * AROWB + c * 16) = ((const uint4*)g_Bn1)[rw * 32 + 16 + c];
    }
#pragma unroll 4
    for (int it = 0; it < 16; it++) {
        int row = wid * 16 + it;
        int n = n0 + row;
        float4 v = make_float4(0.f, 0.f, 0.f, 0.f);
        if (n < N) v = __ldg((const float4*)h + (size_t)n * 32 + lane);
        __half2 h01 = __floats2half2_rn(v.x, v.y);
        __half2 h23 = __floats2half2_rn(v.z, v.w);
        uint2 u; u.x = *(uint32_t*)&h01; u.y = *(uint32_t*)&h23;
        *(uint2*)(smem + NK_A + row * AROWB + lane * 8) = u;
    }
    __syncthreads();

    const int mw = wid & 3, nw = wid >> 2;
    const int mi = lane >> 3, r = lane & 7;
    const uint32_t aBase0 = sb + NK_A
        + (uint32_t)((mw * 32 + (mi & 1) * 8 + r) * APITCH + (mi >> 1) * 8) * 2u;
    const uint32_t aBase1 = aBase0 + 16 * AROWB;
    const uint32_t bBase0 = sb + NK_B0
        + (uint32_t)((nw * 64 + (mi >> 1) * 8 + r) * APITCH + (mi & 1) * 8) * 2u;
    const int gid = lane >> 2, tig = lane & 3;

    float c[2][8][4];
#pragma unroll
    for (int mt = 0; mt < 2; mt++)
#pragma unroll
        for (int nt = 0; nt < 8; nt++)
            c[mt][nt][0] = c[mt][nt][1] = c[mt][nt][2] = c[mt][nt][3] = 0.f;

    // layer 1, k-half 0 (A = h fp16, B = Bn1 half 0)
#pragma unroll
    for (int ks = 0; ks < 8; ks++) {
        uint32_t af0[4], af1[4];
        LDSM_X4(af0, aBase0 + ks * 32);
        LDSM_X4(af1, aBase1 + ks * 32);
        uint32_t kb = bBase0 + ks * 32;
#pragma unroll
        for (int np = 0; np < 4; np++) {
            uint32_t bf[4];
            LDSM_X4(bf, kb);
            mma16816(c[0][2*np],   af0, bf + 0);
            mma16816(c[0][2*np+1], af0, bf + 2);
            mma16816(c[1][2*np],   af1, bf + 0);
            mma16816(c[1][2*np+1], af1, bf + 2);
            kb += 16 * AROWB;
        }
    }
    __syncthreads();
    // overwrite A with agg fp16
#pragma unroll 4
    for (int it = 0; it < 16; it++) {
        int row = wid * 16 + it;
        int n = n0 + row;
        float4 v = make_float4(0.f, 0.f, 0.f, 0.f);
        if (n < N) v = *((const float4*)g_agg + (size_t)n * 32 + lane);
        __half2 h01 = __floats2half2_rn(v.x, v.y);
        __half2 h23 = __floats2half2_rn(v.z, v.w);
        uint2 u; u.x = *(uint32_t*)&h01; u.y = *(uint32_t*)&h23;
        *(uint2*)(smem + NK_A + row * AROWB + lane * 8) = u;
    }
    __syncthreads();
    // layer 1, k-half 1 (A = agg, B = Bn1 half 1)
#pragma unroll
    for (int ks = 0; ks < 8; ks++) {
        uint32_t af0[4], af1[4];
        LDSM_X4(af0, aBase0 + ks * 32);
        LDSM_X4(af1, aBase1 + ks * 32);
        uint32_t kb = bBase0 + (NK_B1 - NK_B0) + ks * 32;
#pragma unroll
        for (int np = 0; np < 4; np++) {
            uint32_t bf[4];
            LDSM_X4(bf, kb);
            mma16816(c[0][2*np],   af0, bf + 0);
            mma16816(c[0][2*np+1], af0, bf + 2);
            mma16816(c[1][2*np],   af1, bf + 0);
            mma16816(c[1][2*np+1], af1, bf + 2);
            kb += 16 * AROWB;
        }
    }
    __syncthreads();
    // t1 = silu(c + nb1) -> fp16 into NK_A; Bn2 -> NK_B0
#pragma unroll
    for (int mt = 0; mt < 2; mt++) {
        int rA = mw * 32 + mt * 16 + gid;
        int rB = rA + 8;
#pragma unroll
        for (int nt = 0; nt < 8; nt++) {
            int col = nw * 64 + nt * 8 + tig * 2;
            float b0 = s_nb1[col], b1 = s_nb1[col + 1];
            *(__half2*)(smem + NK_A + rA * AROWB + col * 2) =
                __floats2half2_rn(silu_f(c[mt][nt][0] + b0), silu_f(c[mt][nt][1] + b1));
            *(__half2*)(smem + NK_A + rB * AROWB + col * 2) =
                __floats2half2_rn(silu_f(c[mt][nt][2] + b0), silu_f(c[mt][nt][3] + b1));
        }
    }
    for (int i = tid; i < 128 * 16; i += 256) {
        int rw = i >> 4, cc = i & 15;
        *(uint4*)(smem + NK_B0 + rw * AROWB + cc * 16) = ((const uint4*)g_Bn2)[rw * 16 + cc];
    }
    __syncthreads();

    // layer 2 (A = t1, B = Bn2)
#pragma unroll
    for (int mt = 0; mt < 2; mt++)
#pragma unroll
        for (int nt = 0; nt < 8; nt++)
            c[mt][nt][0] = c[mt][nt][1] = c[mt][nt][2] = c[mt][nt][3] = 0.f;
#pragma unroll
    for (int ks = 0; ks < 8; ks++) {
        uint32_t af0[4], af1[4];
        LDSM_X4(af0, aBase0 + ks * 32);
        LDSM_X4(af1, aBase1 + ks * 32);
        uint32_t kb = bBase0 + ks * 32;
#pragma unroll
        for (int np = 0; np < 4; np++) {
            uint32_t bf[4];
            LDSM_X4(bf, kb);
            mma16816(c[0][2*np],   af0, bf + 0);
            mma16816(c[0][2*np+1], af0, bf + 2);
            mma16816(c[1][2*np],   af1, bf + 0);
            mma16816(c[1][2*np+1], af1, bf + 2);
            kb += 16 * AROWB;
        }
    }
    __syncthreads();
    // stage o = c + nb2 + h (residual) fp32 into NK_O (pitch 132)
    {
        float* s_o = (float*)(smem + NK_O);
#pragma unroll
        for (int mt = 0; mt < 2; mt++) {
            int rA = mw * 32 + mt * 16 + gid;
            int rB = rA + 8;
            int nA = n0 + rA, nB = n0 + rB;
#pragma unroll
            for (int nt = 0; nt < 8; nt++) {
                int col = nw * 64 + nt * 8 + tig * 2;
                float b0 = s_nb2[col], b1 = s_nb2[col + 1];
                float2 hA = make_float2(0.f, 0.f), hB = make_float2(0.f, 0.f);
                if (nA < N) hA = *(const float2*)(h + (size_t)nA * 128 + col);
                if (nB < N) hB = *(const float2*)(h + (size_t)nB * 128 + col);
                *(float2*)(s_o + rA * 132 + col) =
                    make_float2(c[mt][nt][0] + b0 + hA.x, c[mt][nt][1] + b1 + hA.y);
                *(float2*)(s_o + rB * 132 + col) =
                    make_float2(c[mt][nt][2] + b0 + hB.x, c[mt][nt][3] + b1 + hB.y);
            }
        }
    }
    __syncthreads();
    // LayerNorm per row, write out
    {
        float* s_o = (float*)(smem + NK_O);
#pragma unroll 2
        for (int it = 0; it < 16; it++) {
            int row = wid * 16 + it;
            int n = n0 + row;
            float4 o = *(const float4*)(s_o + row * 132 + lane * 4);
            float s = o.x + o.y + o.z + o.w;
#pragma unroll
            for (int off = 16; off > 0; off >>= 1)
                s += __shfl_xor_sync(0xffffffffu, s, off);
            float mean = s * (1.f / 128.f);
            float dx = o.x - mean, dy = o.y - mean, dz = o.z - mean, dw = o.w - mean;
            float q = dx * dx + dy * dy + dz * dz + dw * dw;
#pragma unroll
            for (int off = 16; off > 0; off >>= 1)
                q += __shfl_xor_sync(0xffffffffu, q, off);
            float inv = rsqrtf(q * (1.f / 128.f) + 1e-5f);
            float4 g4 = *(const float4*)(s_lng + lane * 4);
            float4 bb = *(const float4*)(s_lnb + lane * 4);
            float4 y;
            y.x = dx * inv * g4.x + bb.x;
            y.y = dy * inv * g4.y + bb.y;
            y.z = dz * inv * g4.z + bb.z;
            y.w = dw * inv * g4.w + bb.w;
            if (n < N) ((float4*)out)[(size_t)n * 32 + lane] = y;
        }
    }
}

// ---------------- x output ---------------------------------------------------
__global__ void coord_out_kernel(const float* __restrict__ x,
                                 const float* __restrict__ logit,
                                 float* __restrict__ out_x, int N)
{
    int n = blockIdx.x * blockDim.x + threadIdx.x;
    if (n < N) {
        if (g_skip_coord) {
            out_x[n * 3 + 0] = x[n * 3 + 0];
            out_x[n * 3 + 1] = x[n * 3 + 1];
            out_x[n * 3 + 2] = x[n * 3 + 2];
        } else {
            float scale = 1.f / (1.f + expf(-logit[0]));
            float dg = fmaxf(g_deg[n], 1.f);
            float inv = scale / dg;
            out_x[n * 3 + 0] = x[n * 3 + 0] + g_delta[n * 3 + 0] * inv;
            out_x[n * 3 + 1] = x[n * 3 + 1] + g_delta[n * 3 + 1] * inv;
            out_x[n * 3 + 2] = x[n * 3 + 2] + g_delta[n * 3 + 2] * inv;
        }
    }
}

// ---------------- launcher ----------------------------------------------------
extern "C" void kernel_launch(void* const* d_in, const int* in_sizes, int n_in,
                              void* d_out, int out_size)
{
    const float* h   = (const float*)d_in[0];
    const float* x   = (const float*)d_in[1];
    const void*  ei  = d_in[2];
    const float* ea  = (const float*)d_in[3];
    const float* ew1 = (const float*)d_in[4];
    const float* eb1 = (const float*)d_in[5];
    const float* ew2 = (const float*)d_in[6];
    const float* eb2 = (const float*)d_in[7];
    const float* nw1 = (const float*)d_in[8];
    const float* nb1 = (const float*)d_in[9];
    const float* nw2 = (const float*)d_in[10];
    const float* nb2 = (const float*)d_in[11];
    const float* cw1 = (const float*)d_in[12];
    const float* cb1 = (const float*)d_in[13];
    const float* cw2 = (const float*)d_in[14];
    const float* cb2 = (const float*)d_in[15];
    const float* lgt = (const float*)d_in[16];
    const float* lng = (const float*)d_in[17];
    const float* lnb = (const float*)d_in[18];

    const int N = in_sizes[0] / 128;
    const int E = in_sizes[3] / 4;

    float* out_h = (float*)d_out;
    float* out_x = out_h + (size_t)N * 128;

    cudaFuncSetAttribute(proj_hmma, cudaFuncAttributeMaxDynamicSharedMemorySize,
                         PROJ_SMEM_BYTES);
    cudaFuncSetAttribute(edge_tc_kernel, cudaFuncAttributeMaxDynamicSharedMemorySize,
                         EDGE_SMEM_BYTES);
    cudaFuncSetAttribute(node_hmma, cudaFuncAttributeMaxDynamicSharedMemorySize,
                         NODE_SMEM_BYTES);

    detect_kernel<<<1, 32>>>((const unsigned int*)ei, cw2, cb2);
    zero_kernel<<<(N * 128 + 255) / 256, 256>>>(N);
    build_b_kernel<<<128, 256>>>(ew2, ew1, nw1, nw2);
    proj_hmma<<<(N + 127) / 128, 256, PROJ_SMEM_BYTES>>>(h, eb1, N);
    edge_tc_kernel<<<(E + 127) / 128, 256, EDGE_SMEM_BYTES>>>(
        x, ei, ea, ew1, eb2, cw1, cb1, cw2, cb2, E);
    node_hmma<<<(N + 127) / 128, 256, NODE_SMEM_BYTES>>>(
        h, nb1, nb2, lng, lnb, out_h, N);
    coord_out_kernel<<<(N + 255) / 256, 256>>>(x, lgt, out_x, N);
}